// round 12
// baseline (speedup 1.0000x reference)
#include <cuda_runtime.h>
#include <cuda_bf16.h>
#include <math.h>
#include <stdint.h>

// Problem constants
#define BB 128
#define NN 100
#define DD 2048
#define HH 1024
#define OO 1600
#define AAd 400
#define LL 2048
#define MM (BB*NN)   // 12800

#define OPAD 1792    // OO padded to 256
#define APAD 512     // AAd padded to 256

// ---------------- device scratch (no allocs allowed) ----------------
__device__ __nv_bfloat16 g_xc_hi[(size_t)MM * DD];
__device__ __nv_bfloat16 g_xc_lo[(size_t)MM * DD];
__device__ __nv_bfloat16 g_h1o_hi[(size_t)MM * HH];
__device__ __nv_bfloat16 g_h1o_lo[(size_t)MM * HH];
__device__ __nv_bfloat16 g_h1a_hi[(size_t)MM * HH];
__device__ __nv_bfloat16 g_h1a_lo[(size_t)MM * HH];
__device__ __nv_bfloat16 g_h2o_hi[(size_t)MM * HH];
__device__ __nv_bfloat16 g_h2o_lo[(size_t)MM * HH];
__device__ __nv_bfloat16 g_h2a_hi[(size_t)MM * HH];
__device__ __nv_bfloat16 g_h2a_lo[(size_t)MM * HH];
__device__ __nv_bfloat16 g_wt1o_hi[(size_t)HH * DD];
__device__ __nv_bfloat16 g_wt1o_lo[(size_t)HH * DD];
__device__ __nv_bfloat16 g_wt2o_hi[(size_t)HH * HH];
__device__ __nv_bfloat16 g_wt2o_lo[(size_t)HH * HH];
__device__ __nv_bfloat16 g_wt3o_hi[(size_t)OPAD * HH];
__device__ __nv_bfloat16 g_wt3o_lo[(size_t)OPAD * HH];
__device__ __nv_bfloat16 g_wt1a_hi[(size_t)HH * DD];
__device__ __nv_bfloat16 g_wt1a_lo[(size_t)HH * DD];
__device__ __nv_bfloat16 g_wt2a_hi[(size_t)HH * HH];
__device__ __nv_bfloat16 g_wt2a_lo[(size_t)HH * HH];
__device__ __nv_bfloat16 g_wt3a_hi[(size_t)APAD * HH];
__device__ __nv_bfloat16 g_wt3a_lo[(size_t)APAD * HH];
__device__ float g_lo[(size_t)MM * OO];
__device__ float g_la[(size_t)MM * AAd];
__device__ float2 g_st_o[MM];
__device__ float2 g_st_a[MM];
__device__ int   g_rowmap[MM];
__device__ int   g_rowstart[BB];
__device__ int   g_Meff;
__device__ int   g_desc[LL];

// ---------------- PTX helpers (baseline sm_80+ features only) ----------------
__device__ __forceinline__ uint32_t smem_u32_of(const void* p) {
    uint32_t a;
    asm("{ .reg .u64 t; cvta.to.shared.u64 t, %1; cvt.u32.u64 %0, t; }" : "=r"(a) : "l"(p));
    return a;
}
__device__ __forceinline__ void cp16(uint32_t dst, const void* src) {
    asm volatile("cp.async.cg.shared.global [%0], [%1], 16;" :: "r"(dst), "l"(src) : "memory");
}
__device__ __forceinline__ void cp_commit() {
    asm volatile("cp.async.commit_group;" ::: "memory");
}
template<int N>
__device__ __forceinline__ void cp_wait() {
    asm volatile("cp.async.wait_group %0;" :: "n"(N) : "memory");
}
__device__ __forceinline__ void ldsm4(uint32_t* r, uint32_t addr) {
    asm volatile("ldmatrix.sync.aligned.m8n8.x4.shared.b16 {%0,%1,%2,%3}, [%4];"
        : "=r"(r[0]), "=r"(r[1]), "=r"(r[2]), "=r"(r[3]) : "r"(addr));
}
__device__ __forceinline__ void mma16816(float* c, const uint32_t* a, const uint32_t* b) {
    asm volatile("mma.sync.aligned.m16n8k16.row.col.f32.bf16.bf16.f32 "
        "{%0,%1,%2,%3}, {%4,%5,%6,%7}, {%8,%9}, {%0,%1,%2,%3};"
        : "+f"(c[0]), "+f"(c[1]), "+f"(c[2]), "+f"(c[3])
        : "r"(a[0]), "r"(a[1]), "r"(a[2]), "r"(a[3]), "r"(b[0]), "r"(b[1]));
}

// ---------------- setup: live-row compaction ----------------
__global__ void setup_kernel(const int* __restrict__ num_descs) {
    __shared__ int cnt[BB];
    int b = threadIdx.x;
    int c = num_descs[b];
    if (c < 1) c = 1;
    cnt[b] = c;
    __syncthreads();
    if (b == 0) {
        int acc = 0;
        for (int i = 0; i < BB; i++) { g_rowstart[i] = acc; acc += cnt[i]; }
        g_Meff = acc;
    }
    __syncthreads();
    int start = g_rowstart[b];
    for (int i = 0; i < c; i++) g_rowmap[start + i] = b * NN + i;
}

// ---------------- x compaction + bf16 hi/lo split ----------------
__global__ void xsplit_kernel(const float* __restrict__ x) {
    int r = blockIdx.x;
    int Meff = g_Meff;
    int mceil = (Meff + 127) & ~127;
    if (r >= mceil) return;
    int src = g_rowmap[r < Meff ? r : (Meff - 1)];
    const float4* xp = (const float4*)(x + (size_t)src * DD);
    uint32_t* dh = (uint32_t*)(g_xc_hi + (size_t)r * DD);
    uint32_t* dl = (uint32_t*)(g_xc_lo + (size_t)r * DD);
    for (int i = threadIdx.x; i < DD / 4; i += 256) {
        float4 v = xp[i];
        __nv_bfloat16 h0 = __float2bfloat16(v.x);
        __nv_bfloat16 h1 = __float2bfloat16(v.y);
        __nv_bfloat16 h2 = __float2bfloat16(v.z);
        __nv_bfloat16 h3 = __float2bfloat16(v.w);
        __nv_bfloat16 l0 = __float2bfloat16(v.x - __bfloat162float(h0));
        __nv_bfloat16 l1 = __float2bfloat16(v.y - __bfloat162float(h1));
        __nv_bfloat16 l2 = __float2bfloat16(v.z - __bfloat162float(h2));
        __nv_bfloat16 l3 = __float2bfloat16(v.w - __bfloat162float(h3));
        __nv_bfloat162 ph0; ph0.x = h0; ph0.y = h1;
        __nv_bfloat162 ph1; ph1.x = h2; ph1.y = h3;
        __nv_bfloat162 pl0; pl0.x = l0; pl0.y = l1;
        __nv_bfloat162 pl1; pl1.x = l2; pl1.y = l3;
        dh[2*i]   = *(uint32_t*)&ph0;
        dh[2*i+1] = *(uint32_t*)&ph1;
        dl[2*i]   = *(uint32_t*)&pl0;
        dl[2*i+1] = *(uint32_t*)&pl1;
    }
}

// ---------------- weight transpose + split (2 branches via z), zero-pads ----------------
__global__ void wsplit2_kernel(const float* __restrict__ W0, const float* __restrict__ W1,
                               __nv_bfloat16* T0h, __nv_bfloat16* T0l,
                               __nv_bfloat16* T1h, __nv_bfloat16* T1l,
                               int K, int N) {
    const float* W = blockIdx.z ? W1 : W0;
    __nv_bfloat16* Th = blockIdx.z ? T1h : T0h;
    __nv_bfloat16* Tl = blockIdx.z ? T1l : T0l;
    __shared__ float t[32][33];
    int n0 = blockIdx.x * 32, k0 = blockIdx.y * 32;
    int tx = threadIdx.x, ty = threadIdx.y;
    for (int i = ty; i < 32; i += 8) {
        int n = n0 + tx;
        t[i][tx] = (n < N) ? W[(size_t)(k0 + i) * N + n] : 0.f;
    }
    __syncthreads();
    for (int i = ty; i < 32; i += 8) {
        int n = n0 + i;
        float v = t[tx][i];
        __nv_bfloat16 h = __float2bfloat16(v);
        Th[(size_t)n * K + k0 + tx] = h;
        Tl[(size_t)n * K + k0 + tx] = __float2bfloat16(v - __bfloat162float(h));
    }
}

// ---------------- HMMA split-bf16 GEMM (8 warps of 64x64, staged LDSM) ----------------
// Block tile 128x256, 256 threads = 8 warps (2M x 4N) of 64x64 each.
// K-chunk 64, 2-stage cp.async, two barriers per chunk.
// LDSM is staged BETWEEN MMA groups to keep the tensor pipe fed.
#define STG_BYTES 98304u
#define GEMM_SMEM (2 * 98304)
#define OFF_AL 16384u
#define OFF_BH 32768u
#define OFF_BL 65536u

struct GArgs {
    const __nv_bfloat16 *Ahi0, *Alo0, *Bhi0, *Blo0;
    const __nv_bfloat16 *Ahi1, *Alo1, *Bhi1, *Blo1;
    const float *bias0, *bias1;
    float *Cf0, *Cf1;
    __nv_bfloat16 *Chi0, *Clo0, *Chi1, *Clo1;
    int N0, N1, K;
};

// 128 rows x 64 cols bf16 -> swizzled smem (256 threads, 4 chunks each)
__device__ __forceinline__ void load_tile128(const __nv_bfloat16* __restrict__ g,
                                             int rowStride, int row0, int k0,
                                             uint32_t sdst, int tid) {
    #pragma unroll
    for (int it = 0; it < 4; it++) {
        int v = tid + it * 256;
        int r = v >> 3, cv = v & 7;
        const void* src = g + (size_t)(row0 + r) * rowStride + k0 + cv * 8;
        uint32_t cb = (uint32_t)(cv * 16);
        uint32_t sw = (uint32_t)(r * 128) + (cb ^ (((uint32_t)r & 7u) << 4));
        cp16(sdst + sw, src);
    }
}
// 256 rows x 64 cols bf16 (8 chunks each)
__device__ __forceinline__ void load_tile256(const __nv_bfloat16* __restrict__ g,
                                             int rowStride, int row0, int k0,
                                             uint32_t sdst, int tid) {
    #pragma unroll
    for (int it = 0; it < 8; it++) {
        int v = tid + it * 256;
        int r = v >> 3, cv = v & 7;
        const void* src = g + (size_t)(row0 + r) * rowStride + k0 + cv * 8;
        uint32_t cb = (uint32_t)(cv * 16);
        uint32_t sw = (uint32_t)(r * 128) + (cb ^ (((uint32_t)r & 7u) << 4));
        cp16(sdst + sw, src);
    }
}

__device__ __forceinline__ uint32_t swaddr(uint32_t base, int row, int cb) {
    return base + (uint32_t)(row * 128) + (((uint32_t)cb) ^ (((uint32_t)row & 7u) << 4));
}

// OUTMODE 0: relu + bf16 hi/lo outputs.  OUTMODE 1: fp32 outputs, no relu.
template<int OUTMODE>
__global__ __launch_bounds__(256, 1)
void hgemm(GArgs g)
{
    const int Meff = g_Meff;
    const int rowBase = blockIdx.y * 128;
    if (rowBase >= Meff) return;
    const int z = blockIdx.z;
    const int N = z ? g.N1 : g.N0;
    const int colBase = blockIdx.x * 256;
    if (colBase >= ((N + 255) & ~255)) return;

    const int tid = threadIdx.x;
    const __nv_bfloat16* Ahi = z ? g.Ahi1 : g.Ahi0;
    const __nv_bfloat16* Alo = z ? g.Alo1 : g.Alo0;
    const __nv_bfloat16* Bhi = z ? g.Bhi1 : g.Bhi0;
    const __nv_bfloat16* Blo = z ? g.Blo1 : g.Blo0;
    const float* bias        = z ? g.bias1 : g.bias0;
    float* Cf                = z ? g.Cf1 : g.Cf0;
    __nv_bfloat16* Chi       = z ? g.Chi1 : g.Chi0;
    __nv_bfloat16* Clo       = z ? g.Clo1 : g.Clo0;
    const int K = g.K;

    extern __shared__ char smem[];
    const uint32_t sbase = smem_u32_of(smem);

    const int warp = tid >> 5, lane = tid & 31;
    const int wm = (warp >> 2) * 64;      // 0 / 64
    const int wn = (warp & 3) * 64;       // 0 / 64 / 128 / 192

    float acc[4][8][4];
    #pragma unroll
    for (int i = 0; i < 4; i++)
        #pragma unroll
        for (int j = 0; j < 8; j++)
            #pragma unroll
            for (int c = 0; c < 4; c++) acc[i][j][c] = 0.f;

    const int nk = K >> 6;

    #pragma unroll
    for (int p = 0; p < 2; p++) {
        uint32_t st = sbase + (uint32_t)p * STG_BYTES;
        load_tile128(Ahi, K, rowBase, p * 64, st,          tid);
        load_tile128(Alo, K, rowBase, p * 64, st + OFF_AL, tid);
        load_tile256(Bhi, K, colBase, p * 64, st + OFF_BH, tid);
        load_tile256(Blo, K, colBase, p * 64, st + OFF_BL, tid);
        cp_commit();
    }

    const int aRowL = wm + (lane & 15);
    const int aSel  = (lane >> 4);
    const int bRowL = wn + (lane & 7) + ((lane >> 4) << 3);
    const int bSel  = (lane >> 3) & 1;

    for (int i = 0; i < nk; i++) {
        if (i == nk - 1) cp_wait<0>(); else cp_wait<1>();
        __syncthreads();

        const uint32_t sA  = sbase + (uint32_t)(i & 1) * STG_BYTES;
        const uint32_t sAl = sA + OFF_AL;
        const uint32_t sBh = sA + OFF_BH;
        const uint32_t sBl = sA + OFF_BL;

        #pragma unroll
        for (int kk = 0; kk < 4; kk++) {
            const int aCb = kk * 32 + aSel * 16;
            const int bCb = kk * 32 + bSel * 16;

            uint32_t af[16], bhf[16], blf[16];
            // stage 1 loads: A-hi + B-hi
            #pragma unroll
            for (int mi = 0; mi < 4; mi++)
                ldsm4(&af[mi * 4], swaddr(sA, aRowL + mi * 16, aCb));
            #pragma unroll
            for (int p = 0; p < 4; p++)
                ldsm4(&bhf[p * 4], swaddr(sBh, bRowL + p * 16, bCb));
            // pass 1: hi*hi (32 MMA) — covers stage-2 LDSM below
            #pragma unroll
            for (int mi = 0; mi < 4; mi++)
                #pragma unroll
                for (int ni = 0; ni < 8; ni++)
                    mma16816(acc[mi][ni], &af[mi * 4], &bhf[ni * 2]);
            // stage 2 loads: B-lo
            #pragma unroll
            for (int p = 0; p < 4; p++)
                ldsm4(&blf[p * 4], swaddr(sBl, bRowL + p * 16, bCb));
            // pass 2: hi*lo (32 MMA)
            #pragma unroll
            for (int mi = 0; mi < 4; mi++)
                #pragma unroll
                for (int ni = 0; ni < 8; ni++)
                    mma16816(acc[mi][ni], &af[mi * 4], &blf[ni * 2]);
            // stage 3 loads: A-lo (reuse af regs)
            #pragma unroll
            for (int mi = 0; mi < 4; mi++)
                ldsm4(&af[mi * 4], swaddr(sAl, aRowL + mi * 16, aCb));
            // pass 3: lo*hi (32 MMA)
            #pragma unroll
            for (int mi = 0; mi < 4; mi++)
                #pragma unroll
                for (int ni = 0; ni < 8; ni++)
                    mma16816(acc[mi][ni], &af[mi * 4], &bhf[ni * 2]);
        }

        if (i + 2 < nk) {
            __syncthreads();
            const int k0 = (i + 2) << 6;
            uint32_t st = sbase + (uint32_t)(i & 1) * STG_BYTES;
            load_tile128(Ahi, K, rowBase, k0, st,          tid);
            load_tile128(Alo, K, rowBase, k0, st + OFF_AL, tid);
            load_tile256(Bhi, K, colBase, k0, st + OFF_BH, tid);
            load_tile256(Blo, K, colBase, k0, st + OFF_BL, tid);
            cp_commit();
        }
    }

    // epilogue
    #pragma unroll
    for (int mi = 0; mi < 4; mi++) {
        #pragma unroll
        for (int ni = 0; ni < 8; ni++) {
            const int col = colBase + wn + ni * 8 + (lane & 3) * 2;
            if (col < N) {
                const float2 bv = *(const float2*)(bias + col);
                #pragma unroll
                for (int h = 0; h < 2; h++) {
                    const int row = rowBase + wm + mi * 16 + (lane >> 2) + h * 8;
                    float v0 = acc[mi][ni][h * 2 + 0] + bv.x;
                    float v1 = acc[mi][ni][h * 2 + 1] + bv.y;
                    if (OUTMODE == 0) {
                        v0 = fmaxf(v0, 0.f);
                        v1 = fmaxf(v1, 0.f);
                        __nv_bfloat16 h0 = __float2bfloat16(v0);
                        __nv_bfloat16 h1 = __float2bfloat16(v1);
                        __nv_bfloat16 l0 = __float2bfloat16(v0 - __bfloat162float(h0));
                        __nv_bfloat16 l1 = __float2bfloat16(v1 - __bfloat162float(h1));
                        __nv_bfloat162 ph; ph.x = h0; ph.y = h1;
                        __nv_bfloat162 pl; pl.x = l0; pl.y = l1;
                        *(uint32_t*)(Chi + (size_t)row * N + col) = *(uint32_t*)&ph;
                        *(uint32_t*)(Clo + (size_t)row * N + col) = *(uint32_t*)&pl;
                    } else {
                        float2 v; v.x = v0; v.y = v1;
                        *(float2*)(Cf + (size_t)row * N + col) = v;
                    }
                }
            }
        }
    }
}

// ---------------- per-row softmax stats (both branches, y = branch) ----------------
__global__ void rowstats2_kernel(const float* __restrict__ lg0, const float* __restrict__ lg1,
                                 float2* __restrict__ st0, float2* __restrict__ st1,
                                 int nc0, int nc1)
{
    int r = blockIdx.x;
    if (r >= g_Meff) return;
    const float* p = blockIdx.y ? lg1 : lg0;
    float2* stats  = blockIdx.y ? st1 : st0;
    const int ncols = blockIdx.y ? nc1 : nc0;
    p += (size_t)r * ncols;
    const int tid = threadIdx.x;   // 128
    __shared__ float red[128];

    float mx = -3.402823466e38f;
    for (int j = tid; j < ncols; j += 128) mx = fmaxf(mx, p[j]);
    red[tid] = mx; __syncthreads();
    for (int s = 64; s; s >>= 1) {
        if (tid < s) red[tid] = fmaxf(red[tid], red[tid + s]);
        __syncthreads();
    }
    mx = red[0]; __syncthreads();

    float sum = 0.f;
    for (int j = tid; j < ncols; j += 128) sum += expf(p[j] - mx);
    red[tid] = sum; __syncthreads();
    for (int s = 64; s; s >>= 1) {
        if (tid < s) red[tid] += red[tid + s];
        __syncthreads();
    }
    if (tid == 0) stats[r] = make_float2(mx, red[0]);
}

// ---------------- score + argmax: one warp per label row ----------------
__global__ void score_kernel(const int* __restrict__ label_img,
                             const int* __restrict__ obj_labels,
                             const int* __restrict__ att_labels,
                             const int* __restrict__ num_descs)
{
    int l = blockIdx.x * 8 + (threadIdx.x >> 5);
    int lane = threadIdx.x & 31;
    if (l >= LL) return;
    int b  = label_img[l];
    int nd = num_descs[b];
    int oj = obj_labels[l];
    int aj = att_labels[l];
    int rs = g_rowstart[b];

    float best = -1.0f;
    int   bidx = 0;
    for (int n = lane; n < nd; n += 32) {
        int r = rs + n;
        float2 so = g_st_o[r];
        float2 sa = g_st_a[r];
        float po = expf(g_lo[(size_t)r * OO  + oj] - so.x) / so.y;
        float pa = expf(g_la[(size_t)r * AAd + aj] - sa.x) / sa.y;
        float s = po * pa;
        if (s > best) { best = s; bidx = n; }
    }
    #pragma unroll
    for (int off = 16; off; off >>= 1) {
        float ob = __shfl_down_sync(0xffffffffu, best, off);
        int   oi = __shfl_down_sync(0xffffffffu, bidx, off);
        if (ob > best || (ob == best && oi < bidx)) { best = ob; bidx = oi; }
    }
    if (lane == 0) g_desc[l] = bidx;
}

// ---------------- final gather: softmax of the selected row ----------------
__global__ void gather_kernel(const int* __restrict__ label_img,
                              float* __restrict__ out)
{
    int l = blockIdx.x;
    int b = label_img[l];
    int r = g_rowstart[b] + g_desc[l];

    float2 so = g_st_o[r];
    float inv_o = 1.0f / so.y;
    const float* lo = g_lo + (size_t)r * OO;
    float* oo = out + (size_t)l * OO;
    for (int j = threadIdx.x; j < OO; j += blockDim.x)
        oo[j] = expf(lo[j] - so.x) * inv_o;

    float2 sa = g_st_a[r];
    float inv_a = 1.0f / sa.y;
    const float* la = g_la + (size_t)r * AAd;
    float* oa = out + (size_t)LL * OO + (size_t)l * AAd;
    for (int j = threadIdx.x; j < AAd; j += blockDim.x)
        oa[j] = expf(la[j] - sa.x) * inv_a;
}

// ---------------- launch ----------------
extern "C" void kernel_launch(void* const* d_in, const int* in_sizes, int n_in,
                              void* d_out, int out_size)
{
    const float* x          = (const float*)d_in[0];
    const int*   num_descs  = (const int*)  d_in[1];
    const int*   label_img  = (const int*)  d_in[2];
    const int*   obj_labels = (const int*)  d_in[3];
    const int*   att_labels = (const int*)  d_in[4];
    const float* w1o = (const float*)d_in[5];
    const float* b1o = (const float*)d_in[6];
    const float* w2o = (const float*)d_in[7];
    const float* b2o = (const float*)d_in[8];
    const float* w3o = (const float*)d_in[9];
    const float* b3o = (const float*)d_in[10];
    const float* w1a = (const float*)d_in[11];
    const float* b1a = (const float*)d_in[12];
    const float* w2a = (const float*)d_in[13];
    const float* b2a = (const float*)d_in[14];
    const float* w3a = (const float*)d_in[15];
    const float* b3a = (const float*)d_in[16];
    float* out = (float*)d_out;

    __nv_bfloat16 *xch, *xcl;
    __nv_bfloat16 *h1oh, *h1ol, *h1ah, *h1al, *h2oh, *h2ol, *h2ah, *h2al;
    __nv_bfloat16 *w1oh, *w1ol, *w2oh, *w2ol, *w3oh, *w3ol;
    __nv_bfloat16 *w1ah, *w1al, *w2ah, *w2al, *w3ah, *w3al;
    float *lo, *la;
    float2 *sto, *sta;
    cudaGetSymbolAddress((void**)&xch, g_xc_hi);   cudaGetSymbolAddress((void**)&xcl, g_xc_lo);
    cudaGetSymbolAddress((void**)&h1oh, g_h1o_hi); cudaGetSymbolAddress((void**)&h1ol, g_h1o_lo);
    cudaGetSymbolAddress((void**)&h1ah, g_h1a_hi); cudaGetSymbolAddress((void**)&h1al, g_h1a_lo);
    cudaGetSymbolAddress((void**)&h2oh, g_h2o_hi); cudaGetSymbolAddress((void**)&h2ol, g_h2o_lo);
    cudaGetSymbolAddress((void**)&h2ah, g_h2a_hi); cudaGetSymbolAddress((void**)&h2al, g_h2a_lo);
    cudaGetSymbolAddress((void**)&w1oh, g_wt1o_hi); cudaGetSymbolAddress((void**)&w1ol, g_wt1o_lo);
    cudaGetSymbolAddress((void**)&w2oh, g_wt2o_hi); cudaGetSymbolAddress((void**)&w2ol, g_wt2o_lo);
    cudaGetSymbolAddress((void**)&w3oh, g_wt3o_hi); cudaGetSymbolAddress((void**)&w3ol, g_wt3o_lo);
    cudaGetSymbolAddress((void**)&w1ah, g_wt1a_hi); cudaGetSymbolAddress((void**)&w1al, g_wt1a_lo);
    cudaGetSymbolAddress((void**)&w2ah, g_wt2a_hi); cudaGetSymbolAddress((void**)&w2al, g_wt2a_lo);
    cudaGetSymbolAddress((void**)&w3ah, g_wt3a_hi); cudaGetSymbolAddress((void**)&w3al, g_wt3a_lo);
    cudaGetSymbolAddress((void**)&lo,  g_lo);
    cudaGetSymbolAddress((void**)&la,  g_la);
    cudaGetSymbolAddress((void**)&sto, g_st_o);
    cudaGetSymbolAddress((void**)&sta, g_st_a);

    cudaFuncSetAttribute(hgemm<0>, cudaFuncAttributeMaxDynamicSharedMemorySize, GEMM_SMEM);
    cudaFuncSetAttribute(hgemm<1>, cudaFuncAttributeMaxDynamicSharedMemorySize, GEMM_SMEM);

    const int MT = MM / 128;  // 100 M tiles max; blocks past g_Meff exit
    dim3 wb(32, 8);

    // 1
    setup_kernel<<<1, BB>>>(num_descs);
    // 2
    xsplit_kernel<<<MM, 256>>>(x);
    // 3: w1 prep, both branches
    wsplit2_kernel<<<dim3(HH/32, DD/32, 2), wb>>>(w1o, w1a, w1oh, w1ol, w1ah, w1al, DD, HH);
    // 4: layer-1 GEMM (profiled by ncu)
    GArgs a1 = { xch, xcl, w1oh, w1ol,
                 xch, xcl, w1ah, w1al,
                 b1o, b1a, nullptr, nullptr,
                 h1oh, h1ol, h1ah, h1al, HH, HH, DD };
    hgemm<0><<<dim3(HH/256, MT, 2), 256, GEMM_SMEM>>>(a1);
    // 5
    wsplit2_kernel<<<dim3(HH/32, HH/32, 2), wb>>>(w2o, w2a, w2oh, w2ol, w2ah, w2al, HH, HH);
    // 6: layer-2 GEMM
    GArgs a2 = { h1oh, h1ol, w2oh, w2ol,
                 h1ah, h1al, w2ah, w2al,
                 b2o, b2a, nullptr, nullptr,
                 h2oh, h2ol, h2ah, h2al, HH, HH, HH };
    hgemm<0><<<dim3(HH/256, MT, 2), 256, GEMM_SMEM>>>(a2);
    // 7, 8: w3 prep (pads zeroed)
    wsplit2_kernel<<<dim3(OPAD/32, HH/32, 1), wb>>>(w3o, w3o, w3oh, w3ol, w3oh, w3ol, HH, OO);
    wsplit2_kernel<<<dim3(APAD/32, HH/32, 1), wb>>>(w3a, w3a, w3ah, w3al, w3ah, w3al, HH, AAd);
    // 9: layer-3, both branches merged (z=0 obj N=OO, z=1 att N=AAd)
    GArgs a3 = { h2oh, h2ol, w3oh, w3ol,
                 h2ah, h2al, w3ah, w3al,
                 b3o, b3a, lo, la,
                 nullptr, nullptr, nullptr, nullptr, OO, AAd, HH };
    hgemm<1><<<dim3(OPAD/256, MT, 2), 256, GEMM_SMEM>>>(a3);

    rowstats2_kernel<<<dim3(MM, 2), 128>>>(lo, la, sto, sta, OO, AAd);
    score_kernel<<<(LL + 7) / 8, 256>>>(label_img, obj_labels, att_labels, num_descs);
    gather_kernel<<<LL, 256>>>(label_img, out);
}

// round 13
// speedup vs baseline: 1.5236x; 1.5236x over previous
#include <cuda_runtime.h>
#include <cuda_bf16.h>
#include <math.h>
#include <stdint.h>

// Problem constants
#define BB 128
#define NN 100
#define DD 2048
#define HH 1024
#define OO 1600
#define AAd 400
#define LL 2048
#define MM (BB*NN)   // 12800

#define OPAD 1792    // OO padded to 256
#define APAD 512     // AAd padded to 256

// ---------------- device scratch (no allocs allowed) ----------------
__device__ __nv_bfloat16 g_xc_hi[(size_t)MM * DD];
__device__ __nv_bfloat16 g_xc_lo[(size_t)MM * DD];
__device__ __nv_bfloat16 g_h1o_hi[(size_t)MM * HH];
__device__ __nv_bfloat16 g_h1o_lo[(size_t)MM * HH];
__device__ __nv_bfloat16 g_h1a_hi[(size_t)MM * HH];
__device__ __nv_bfloat16 g_h1a_lo[(size_t)MM * HH];
__device__ __nv_bfloat16 g_h2o_hi[(size_t)MM * HH];
__device__ __nv_bfloat16 g_h2o_lo[(size_t)MM * HH];
__device__ __nv_bfloat16 g_h2a_hi[(size_t)MM * HH];
__device__ __nv_bfloat16 g_h2a_lo[(size_t)MM * HH];
__device__ __nv_bfloat16 g_wt1o_hi[(size_t)HH * DD];
__device__ __nv_bfloat16 g_wt1o_lo[(size_t)HH * DD];
__device__ __nv_bfloat16 g_wt2o_hi[(size_t)HH * HH];
__device__ __nv_bfloat16 g_wt2o_lo[(size_t)HH * HH];
__device__ __nv_bfloat16 g_wt3o_hi[(size_t)OPAD * HH];
__device__ __nv_bfloat16 g_wt3o_lo[(size_t)OPAD * HH];
__device__ __nv_bfloat16 g_wt1a_hi[(size_t)HH * DD];
__device__ __nv_bfloat16 g_wt1a_lo[(size_t)HH * DD];
__device__ __nv_bfloat16 g_wt2a_hi[(size_t)HH * HH];
__device__ __nv_bfloat16 g_wt2a_lo[(size_t)HH * HH];
__device__ __nv_bfloat16 g_wt3a_hi[(size_t)APAD * HH];
__device__ __nv_bfloat16 g_wt3a_lo[(size_t)APAD * HH];
__device__ float g_lo[(size_t)MM * OO];
__device__ float g_la[(size_t)MM * AAd];
__device__ float2 g_st_o[MM];
__device__ float2 g_st_a[MM];
__device__ int   g_rowmap[MM];
__device__ int   g_rowstart[BB];
__device__ int   g_Meff;
__device__ int   g_desc[LL];

// ---------------- PTX helpers (baseline sm_80+ features only) ----------------
__device__ __forceinline__ uint32_t smem_u32_of(const void* p) {
    uint32_t a;
    asm("{ .reg .u64 t; cvta.to.shared.u64 t, %1; cvt.u32.u64 %0, t; }" : "=r"(a) : "l"(p));
    return a;
}
__device__ __forceinline__ void cp16(uint32_t dst, const void* src) {
    asm volatile("cp.async.cg.shared.global [%0], [%1], 16;" :: "r"(dst), "l"(src) : "memory");
}
__device__ __forceinline__ void cp_commit() {
    asm volatile("cp.async.commit_group;" ::: "memory");
}
template<int N>
__device__ __forceinline__ void cp_wait() {
    asm volatile("cp.async.wait_group %0;" :: "n"(N) : "memory");
}
__device__ __forceinline__ void ldsm4(uint32_t* r, uint32_t addr) {
    asm volatile("ldmatrix.sync.aligned.m8n8.x4.shared.b16 {%0,%1,%2,%3}, [%4];"
        : "=r"(r[0]), "=r"(r[1]), "=r"(r[2]), "=r"(r[3]) : "r"(addr));
}
__device__ __forceinline__ void mma16816(float* c, const uint32_t* a, const uint32_t* b) {
    asm volatile("mma.sync.aligned.m16n8k16.row.col.f32.bf16.bf16.f32 "
        "{%0,%1,%2,%3}, {%4,%5,%6,%7}, {%8,%9}, {%0,%1,%2,%3};"
        : "+f"(c[0]), "+f"(c[1]), "+f"(c[2]), "+f"(c[3])
        : "r"(a[0]), "r"(a[1]), "r"(a[2]), "r"(a[3]), "r"(b[0]), "r"(b[1]));
}

// ---------------- setup: live-row compaction ----------------
__global__ void setup_kernel(const int* __restrict__ num_descs) {
    __shared__ int cnt[BB];
    int b = threadIdx.x;
    int c = num_descs[b];
    if (c < 1) c = 1;
    cnt[b] = c;
    __syncthreads();
    if (b == 0) {
        int acc = 0;
        for (int i = 0; i < BB; i++) { g_rowstart[i] = acc; acc += cnt[i]; }
        g_Meff = acc;
    }
    __syncthreads();
    int start = g_rowstart[b];
    for (int i = 0; i < c; i++) g_rowmap[start + i] = b * NN + i;
}

// ---------------- x compaction + bf16 hi/lo split ----------------
__global__ void xsplit_kernel(const float* __restrict__ x) {
    int r = blockIdx.x;
    int Meff = g_Meff;
    int mceil = (Meff + 127) & ~127;
    if (r >= mceil) return;
    int src = g_rowmap[r < Meff ? r : (Meff - 1)];
    const float4* xp = (const float4*)(x + (size_t)src * DD);
    uint32_t* dh = (uint32_t*)(g_xc_hi + (size_t)r * DD);
    uint32_t* dl = (uint32_t*)(g_xc_lo + (size_t)r * DD);
    for (int i = threadIdx.x; i < DD / 4; i += 256) {
        float4 v = xp[i];
        __nv_bfloat16 h0 = __float2bfloat16(v.x);
        __nv_bfloat16 h1 = __float2bfloat16(v.y);
        __nv_bfloat16 h2 = __float2bfloat16(v.z);
        __nv_bfloat16 h3 = __float2bfloat16(v.w);
        __nv_bfloat16 l0 = __float2bfloat16(v.x - __bfloat162float(h0));
        __nv_bfloat16 l1 = __float2bfloat16(v.y - __bfloat162float(h1));
        __nv_bfloat16 l2 = __float2bfloat16(v.z - __bfloat162float(h2));
        __nv_bfloat16 l3 = __float2bfloat16(v.w - __bfloat162float(h3));
        __nv_bfloat162 ph0; ph0.x = h0; ph0.y = h1;
        __nv_bfloat162 ph1; ph1.x = h2; ph1.y = h3;
        __nv_bfloat162 pl0; pl0.x = l0; pl0.y = l1;
        __nv_bfloat162 pl1; pl1.x = l2; pl1.y = l3;
        dh[2*i]   = *(uint32_t*)&ph0;
        dh[2*i+1] = *(uint32_t*)&ph1;
        dl[2*i]   = *(uint32_t*)&pl0;
        dl[2*i+1] = *(uint32_t*)&pl1;
    }
}

// ---------------- weight transpose + split (2 branches via z), zero-pads ----------------
__global__ void wsplit2_kernel(const float* __restrict__ W0, const float* __restrict__ W1,
                               __nv_bfloat16* T0h, __nv_bfloat16* T0l,
                               __nv_bfloat16* T1h, __nv_bfloat16* T1l,
                               int K, int N) {
    const float* W = blockIdx.z ? W1 : W0;
    __nv_bfloat16* Th = blockIdx.z ? T1h : T0h;
    __nv_bfloat16* Tl = blockIdx.z ? T1l : T0l;
    __shared__ float t[32][33];
    int n0 = blockIdx.x * 32, k0 = blockIdx.y * 32;
    int tx = threadIdx.x, ty = threadIdx.y;
    for (int i = ty; i < 32; i += 8) {
        int n = n0 + tx;
        t[i][tx] = (n < N) ? W[(size_t)(k0 + i) * N + n] : 0.f;
    }
    __syncthreads();
    for (int i = ty; i < 32; i += 8) {
        int n = n0 + i;
        float v = t[tx][i];
        __nv_bfloat16 h = __float2bfloat16(v);
        Th[(size_t)n * K + k0 + tx] = h;
        Tl[(size_t)n * K + k0 + tx] = __float2bfloat16(v - __bfloat162float(h));
    }
}

// ---------------- HMMA split-bf16 GEMM (8 warps of 64x64) ----------------
// Block tile 128x256, 256 threads = 8 warps (2M x 4N) of 64x64 each.
// K-chunk 64, 2-stage cp.async, two barriers per chunk (best measured config).
#define STG_BYTES 98304u
#define GEMM_SMEM (2 * 98304)
#define OFF_AL 16384u
#define OFF_BH 32768u
#define OFF_BL 65536u

struct GArgs {
    const __nv_bfloat16 *Ahi0, *Alo0, *Bhi0, *Blo0;
    const __nv_bfloat16 *Ahi1, *Alo1, *Bhi1, *Blo1;
    const float *bias0, *bias1;
    float *Cf0, *Cf1;
    __nv_bfloat16 *Chi0, *Clo0, *Chi1, *Clo1;
    int N0, N1, K;
};

// 128 rows x 64 cols bf16 -> swizzled smem (256 threads, 4 chunks each)
__device__ __forceinline__ void load_tile128(const __nv_bfloat16* __restrict__ g,
                                             int rowStride, int row0, int k0,
                                             uint32_t sdst, int tid) {
    #pragma unroll
    for (int it = 0; it < 4; it++) {
        int v = tid + it * 256;
        int r = v >> 3, cv = v & 7;
        const void* src = g + (size_t)(row0 + r) * rowStride + k0 + cv * 8;
        uint32_t cb = (uint32_t)(cv * 16);
        uint32_t sw = (uint32_t)(r * 128) + (cb ^ (((uint32_t)r & 7u) << 4));
        cp16(sdst + sw, src);
    }
}
// 256 rows x 64 cols bf16 (8 chunks each)
__device__ __forceinline__ void load_tile256(const __nv_bfloat16* __restrict__ g,
                                             int rowStride, int row0, int k0,
                                             uint32_t sdst, int tid) {
    #pragma unroll
    for (int it = 0; it < 8; it++) {
        int v = tid + it * 256;
        int r = v >> 3, cv = v & 7;
        const void* src = g + (size_t)(row0 + r) * rowStride + k0 + cv * 8;
        uint32_t cb = (uint32_t)(cv * 16);
        uint32_t sw = (uint32_t)(r * 128) + (cb ^ (((uint32_t)r & 7u) << 4));
        cp16(sdst + sw, src);
    }
}

__device__ __forceinline__ uint32_t swaddr(uint32_t base, int row, int cb) {
    return base + (uint32_t)(row * 128) + (((uint32_t)cb) ^ (((uint32_t)row & 7u) << 4));
}

// OUTMODE 0: relu + bf16 hi/lo outputs.  OUTMODE 1: fp32 outputs, no relu.
template<int OUTMODE>
__global__ __launch_bounds__(256, 1)
void hgemm(GArgs g)
{
    const int Meff = g_Meff;
    const int rowBase = blockIdx.y * 128;
    if (rowBase >= Meff) return;
    const int z = blockIdx.z;
    const int N = z ? g.N1 : g.N0;
    const int colBase = blockIdx.x * 256;
    if (colBase >= ((N + 255) & ~255)) return;

    const int tid = threadIdx.x;
    const __nv_bfloat16* Ahi = z ? g.Ahi1 : g.Ahi0;
    const __nv_bfloat16* Alo = z ? g.Alo1 : g.Alo0;
    const __nv_bfloat16* Bhi = z ? g.Bhi1 : g.Bhi0;
    const __nv_bfloat16* Blo = z ? g.Blo1 : g.Blo0;
    const float* bias        = z ? g.bias1 : g.bias0;
    float* Cf                = z ? g.Cf1 : g.Cf0;
    __nv_bfloat16* Chi       = z ? g.Chi1 : g.Chi0;
    __nv_bfloat16* Clo       = z ? g.Clo1 : g.Clo0;
    const int K = g.K;

    extern __shared__ char smem[];
    const uint32_t sbase = smem_u32_of(smem);

    const int warp = tid >> 5, lane = tid & 31;
    const int wm = (warp >> 2) * 64;      // 0 / 64
    const int wn = (warp & 3) * 64;       // 0 / 64 / 128 / 192

    float acc[4][8][4];
    #pragma unroll
    for (int i = 0; i < 4; i++)
        #pragma unroll
        for (int j = 0; j < 8; j++)
            #pragma unroll
            for (int c = 0; c < 4; c++) acc[i][j][c] = 0.f;

    const int nk = K >> 6;

    #pragma unroll
    for (int p = 0; p < 2; p++) {
        uint32_t st = sbase + (uint32_t)p * STG_BYTES;
        load_tile128(Ahi, K, rowBase, p * 64, st,          tid);
        load_tile128(Alo, K, rowBase, p * 64, st + OFF_AL, tid);
        load_tile256(Bhi, K, colBase, p * 64, st + OFF_BH, tid);
        load_tile256(Blo, K, colBase, p * 64, st + OFF_BL, tid);
        cp_commit();
    }

    const int aRowL = wm + (lane & 15);
    const int aSel  = (lane >> 4);
    const int bRowL = wn + (lane & 7) + ((lane >> 4) << 3);
    const int bSel  = (lane >> 3) & 1;

    for (int i = 0; i < nk; i++) {
        if (i == nk - 1) cp_wait<0>(); else cp_wait<1>();
        __syncthreads();

        const uint32_t sA  = sbase + (uint32_t)(i & 1) * STG_BYTES;
        const uint32_t sAl = sA + OFF_AL;
        const uint32_t sBh = sA + OFF_BH;
        const uint32_t sBl = sA + OFF_BL;

        #pragma unroll
        for (int kk = 0; kk < 4; kk++) {
            const int aCb = kk * 32 + aSel * 16;
            const int bCb = kk * 32 + bSel * 16;

            uint32_t af[16], bhf[16], blf[16];
            #pragma unroll
            for (int mi = 0; mi < 4; mi++)
                ldsm4(&af[mi * 4], swaddr(sA, aRowL + mi * 16, aCb));
            #pragma unroll
            for (int p = 0; p < 4; p++) {
                ldsm4(&bhf[p * 4], swaddr(sBh, bRowL + p * 16, bCb));
                ldsm4(&blf[p * 4], swaddr(sBl, bRowL + p * 16, bCb));
            }
            // hi*hi and hi*lo
            #pragma unroll
            for (int mi = 0; mi < 4; mi++)
                #pragma unroll
                for (int ni = 0; ni < 8; ni++) {
                    mma16816(acc[mi][ni], &af[mi * 4], &bhf[ni * 2]);
                    mma16816(acc[mi][ni], &af[mi * 4], &blf[ni * 2]);
                }
            // lo*hi
            #pragma unroll
            for (int mi = 0; mi < 4; mi++)
                ldsm4(&af[mi * 4], swaddr(sAl, aRowL + mi * 16, aCb));
            #pragma unroll
            for (int mi = 0; mi < 4; mi++)
                #pragma unroll
                for (int ni = 0; ni < 8; ni++)
                    mma16816(acc[mi][ni], &af[mi * 4], &bhf[ni * 2]);
        }

        if (i + 2 < nk) {
            __syncthreads();
            const int k0 = (i + 2) << 6;
            uint32_t st = sbase + (uint32_t)(i & 1) * STG_BYTES;
            load_tile128(Ahi, K, rowBase, k0, st,          tid);
            load_tile128(Alo, K, rowBase, k0, st + OFF_AL, tid);
            load_tile256(Bhi, K, colBase, k0, st + OFF_BH, tid);
            load_tile256(Blo, K, colBase, k0, st + OFF_BL, tid);
            cp_commit();
        }
    }

    // epilogue
    #pragma unroll
    for (int mi = 0; mi < 4; mi++) {
        #pragma unroll
        for (int ni = 0; ni < 8; ni++) {
            const int col = colBase + wn + ni * 8 + (lane & 3) * 2;
            if (col < N) {
                const float2 bv = *(const float2*)(bias + col);
                #pragma unroll
                for (int h = 0; h < 2; h++) {
                    const int row = rowBase + wm + mi * 16 + (lane >> 2) + h * 8;
                    float v0 = acc[mi][ni][h * 2 + 0] + bv.x;
                    float v1 = acc[mi][ni][h * 2 + 1] + bv.y;
                    if (OUTMODE == 0) {
                        v0 = fmaxf(v0, 0.f);
                        v1 = fmaxf(v1, 0.f);
                        __nv_bfloat16 h0 = __float2bfloat16(v0);
                        __nv_bfloat16 h1 = __float2bfloat16(v1);
                        __nv_bfloat16 l0 = __float2bfloat16(v0 - __bfloat162float(h0));
                        __nv_bfloat16 l1 = __float2bfloat16(v1 - __bfloat162float(h1));
                        __nv_bfloat162 ph; ph.x = h0; ph.y = h1;
                        __nv_bfloat162 pl; pl.x = l0; pl.y = l1;
                        *(uint32_t*)(Chi + (size_t)row * N + col) = *(uint32_t*)&ph;
                        *(uint32_t*)(Clo + (size_t)row * N + col) = *(uint32_t*)&pl;
                    } else {
                        float2 v; v.x = v0; v.y = v1;
                        *(float2*)(Cf + (size_t)row * N + col) = v;
                    }
                }
            }
        }
    }
}

// ---------------- per-row softmax stats (both branches, y = branch) ----------------
__global__ void rowstats2_kernel(const float* __restrict__ lg0, const float* __restrict__ lg1,
                                 float2* __restrict__ st0, float2* __restrict__ st1,
                                 int nc0, int nc1)
{
    int r = blockIdx.x;
    if (r >= g_Meff) return;
    const float* p = blockIdx.y ? lg1 : lg0;
    float2* stats  = blockIdx.y ? st1 : st0;
    const int ncols = blockIdx.y ? nc1 : nc0;
    p += (size_t)r * ncols;
    const int tid = threadIdx.x;   // 128
    __shared__ float red[128];

    float mx = -3.402823466e38f;
    for (int j = tid; j < ncols; j += 128) mx = fmaxf(mx, p[j]);
    red[tid] = mx; __syncthreads();
    for (int s = 64; s; s >>= 1) {
        if (tid < s) red[tid] = fmaxf(red[tid], red[tid + s]);
        __syncthreads();
    }
    mx = red[0]; __syncthreads();

    float sum = 0.f;
    for (int j = tid; j < ncols; j += 128) sum += expf(p[j] - mx);
    red[tid] = sum; __syncthreads();
    for (int s = 64; s; s >>= 1) {
        if (tid < s) red[tid] += red[tid + s];
        __syncthreads();
    }
    if (tid == 0) stats[r] = make_float2(mx, red[0]);
}

// ---------------- score + argmax: one warp per label row ----------------
__global__ void score_kernel(const int* __restrict__ label_img,
                             const int* __restrict__ obj_labels,
                             const int* __restrict__ att_labels,
                             const int* __restrict__ num_descs)
{
    int l = blockIdx.x * 8 + (threadIdx.x >> 5);
    int lane = threadIdx.x & 31;
    if (l >= LL) return;
    int b  = label_img[l];
    int nd = num_descs[b];
    int oj = obj_labels[l];
    int aj = att_labels[l];
    int rs = g_rowstart[b];

    float best = -1.0f;
    int   bidx = 0;
    for (int n = lane; n < nd; n += 32) {
        int r = rs + n;
        float2 so = g_st_o[r];
        float2 sa = g_st_a[r];
        float po = expf(g_lo[(size_t)r * OO  + oj] - so.x) / so.y;
        float pa = expf(g_la[(size_t)r * AAd + aj] - sa.x) / sa.y;
        float s = po * pa;
        if (s > best) { best = s; bidx = n; }
    }
    #pragma unroll
    for (int off = 16; off; off >>= 1) {
        float ob = __shfl_down_sync(0xffffffffu, best, off);
        int   oi = __shfl_down_sync(0xffffffffu, bidx, off);
        if (ob > best || (ob == best && oi < bidx)) { best = ob; bidx = oi; }
    }
    if (lane == 0) g_desc[l] = bidx;
}

// ---------------- final gather: softmax of the selected row ----------------
__global__ void gather_kernel(const int* __restrict__ label_img,
                              float* __restrict__ out)
{
    int l = blockIdx.x;
    int b = label_img[l];
    int r = g_rowstart[b] + g_desc[l];

    float2 so = g_st_o[r];
    float inv_o = 1.0f / so.y;
    const float* lo = g_lo + (size_t)r * OO;
    float* oo = out + (size_t)l * OO;
    for (int j = threadIdx.x; j < OO; j += blockDim.x)
        oo[j] = expf(lo[j] - so.x) * inv_o;

    float2 sa = g_st_a[r];
    float inv_a = 1.0f / sa.y;
    const float* la = g_la + (size_t)r * AAd;
    float* oa = out + (size_t)LL * OO + (size_t)l * AAd;
    for (int j = threadIdx.x; j < AAd; j += blockDim.x)
        oa[j] = expf(la[j] - sa.x) * inv_a;
}

// ---------------- launch ----------------
extern "C" void kernel_launch(void* const* d_in, const int* in_sizes, int n_in,
                              void* d_out, int out_size)
{
    const float* x          = (const float*)d_in[0];
    const int*   num_descs  = (const int*)  d_in[1];
    const int*   label_img  = (const int*)  d_in[2];
    const int*   obj_labels = (const int*)  d_in[3];
    const int*   att_labels = (const int*)  d_in[4];
    const float* w1o = (const float*)d_in[5];
    const float* b1o = (const float*)d_in[6];
    const float* w2o = (const float*)d_in[7];
    const float* b2o = (const float*)d_in[8];
    const float* w3o = (const float*)d_in[9];
    const float* b3o = (const float*)d_in[10];
    const float* w1a = (const float*)d_in[11];
    const float* b1a = (const float*)d_in[12];
    const float* w2a = (const float*)d_in[13];
    const float* b2a = (const float*)d_in[14];
    const float* w3a = (const float*)d_in[15];
    const float* b3a = (const float*)d_in[16];
    float* out = (float*)d_out;

    __nv_bfloat16 *xch, *xcl;
    __nv_bfloat16 *h1oh, *h1ol, *h1ah, *h1al, *h2oh, *h2ol, *h2ah, *h2al;
    __nv_bfloat16 *w1oh, *w1ol, *w2oh, *w2ol, *w3oh, *w3ol;
    __nv_bfloat16 *w1ah, *w1al, *w2ah, *w2al, *w3ah, *w3al;
    float *lo, *la;
    float2 *sto, *sta;
    cudaGetSymbolAddress((void**)&xch, g_xc_hi);   cudaGetSymbolAddress((void**)&xcl, g_xc_lo);
    cudaGetSymbolAddress((void**)&h1oh, g_h1o_hi); cudaGetSymbolAddress((void**)&h1ol, g_h1o_lo);
    cudaGetSymbolAddress((void**)&h1ah, g_h1a_hi); cudaGetSymbolAddress((void**)&h1al, g_h1a_lo);
    cudaGetSymbolAddress((void**)&h2oh, g_h2o_hi); cudaGetSymbolAddress((void**)&h2ol, g_h2o_lo);
    cudaGetSymbolAddress((void**)&h2ah, g_h2a_hi); cudaGetSymbolAddress((void**)&h2al, g_h2a_lo);
    cudaGetSymbolAddress((void**)&w1oh, g_wt1o_hi); cudaGetSymbolAddress((void**)&w1ol, g_wt1o_lo);
    cudaGetSymbolAddress((void**)&w2oh, g_wt2o_hi); cudaGetSymbolAddress((void**)&w2ol, g_wt2o_lo);
    cudaGetSymbolAddress((void**)&w3oh, g_wt3o_hi); cudaGetSymbolAddress((void**)&w3ol, g_wt3o_lo);
    cudaGetSymbolAddress((void**)&w1ah, g_wt1a_hi); cudaGetSymbolAddress((void**)&w1al, g_wt1a_lo);
    cudaGetSymbolAddress((void**)&w2ah, g_wt2a_hi); cudaGetSymbolAddress((void**)&w2al, g_wt2a_lo);
    cudaGetSymbolAddress((void**)&w3ah, g_wt3a_hi); cudaGetSymbolAddress((void**)&w3al, g_wt3a_lo);
    cudaGetSymbolAddress((void**)&lo,  g_lo);
    cudaGetSymbolAddress((void**)&la,  g_la);
    cudaGetSymbolAddress((void**)&sto, g_st_o);
    cudaGetSymbolAddress((void**)&sta, g_st_a);

    cudaFuncSetAttribute(hgemm<0>, cudaFuncAttributeMaxDynamicSharedMemorySize, GEMM_SMEM);
    cudaFuncSetAttribute(hgemm<1>, cudaFuncAttributeMaxDynamicSharedMemorySize, GEMM_SMEM);

    const int MT = MM / 128;  // 100 M tiles max; blocks past g_Meff exit
    dim3 wb(32, 8);

    // 1
    setup_kernel<<<1, BB>>>(num_descs);
    // 2
    xsplit_kernel<<<MM, 256>>>(x);
    // 3: w1 prep, both branches
    wsplit2_kernel<<<dim3(HH/32, DD/32, 2), wb>>>(w1o, w1a, w1oh, w1ol, w1ah, w1al, DD, HH);
    // 4: layer-1 GEMM (profiled by ncu)
    GArgs a1 = { xch, xcl, w1oh, w1ol,
                 xch, xcl, w1ah, w1al,
                 b1o, b1a, nullptr, nullptr,
                 h1oh, h1ol, h1ah, h1al, HH, HH, DD };
    hgemm<0><<<dim3(HH/256, MT, 2), 256, GEMM_SMEM>>>(a1);
    // 5
    wsplit2_kernel<<<dim3(HH/32, HH/32, 2), wb>>>(w2o, w2a, w2oh, w2ol, w2ah, w2al, HH, HH);
    // 6: layer-2 GEMM
    GArgs a2 = { h1oh, h1ol, w2oh, w2ol,
                 h1ah, h1al, w2ah, w2al,
                 b2o, b2a, nullptr, nullptr,
                 h2oh, h2ol, h2ah, h2al, HH, HH, HH };
    hgemm<0><<<dim3(HH/256, MT, 2), 256, GEMM_SMEM>>>(a2);
    // 7, 8: w3 prep (pads zeroed)
    wsplit2_kernel<<<dim3(OPAD/32, HH/32, 1), wb>>>(w3o, w3o, w3oh, w3ol, w3oh, w3ol, HH, OO);
    wsplit2_kernel<<<dim3(APAD/32, HH/32, 1), wb>>>(w3a, w3a, w3ah, w3al, w3ah, w3al, HH, AAd);
    // 9: layer-3, both branches merged (z=0 obj N=OO, z=1 att N=AAd)
    GArgs a3 = { h2oh, h2ol, w3oh, w3ol,
                 h2ah, h2al, w3ah, w3al,
                 b3o, b3a, lo, la,
                 nullptr, nullptr, nullptr, nullptr, OO, AAd, HH };
    hgemm<1><<<dim3(OPAD/256, MT, 2), 256, GEMM_SMEM>>>(a3);

    rowstats2_kernel<<<dim3(MM, 2), 128>>>(lo, la, sto, sta, OO, AAd);
    score_kernel<<<(LL + 7) / 8, 256>>>(label_img, obj_labels, att_labels, num_descs);
    gather_kernel<<<LL, 256>>>(label_img, out);
}

// round 14
// speedup vs baseline: 1.5354x; 1.0077x over previous
#include <cuda_runtime.h>
#include <cuda_bf16.h>
#include <math.h>
#include <stdint.h>

// Problem constants
#define BB 128
#define NN 100
#define DD 2048
#define HH 1024
#define OO 1600
#define AAd 400
#define LL 2048
#define MM (BB*NN)   // 12800

#define OPAD 1792    // OO padded to 256
#define APAD 512     // AAd padded to 256

// ---------------- device scratch (no allocs allowed) ----------------
__device__ __nv_bfloat16 g_xc_hi[(size_t)MM * DD];
__device__ __nv_bfloat16 g_xc_lo[(size_t)MM * DD];
__device__ __nv_bfloat16 g_h1o_hi[(size_t)MM * HH];
__device__ __nv_bfloat16 g_h1o_lo[(size_t)MM * HH];
__device__ __nv_bfloat16 g_h1a_hi[(size_t)MM * HH];
__device__ __nv_bfloat16 g_h1a_lo[(size_t)MM * HH];
__device__ __nv_bfloat16 g_h2o_hi[(size_t)MM * HH];
__device__ __nv_bfloat16 g_h2o_lo[(size_t)MM * HH];
__device__ __nv_bfloat16 g_h2a_hi[(size_t)MM * HH];
__device__ __nv_bfloat16 g_h2a_lo[(size_t)MM * HH];
__device__ __nv_bfloat16 g_wt1o_hi[(size_t)HH * DD];
__device__ __nv_bfloat16 g_wt1o_lo[(size_t)HH * DD];
__device__ __nv_bfloat16 g_wt2o_hi[(size_t)HH * HH];
__device__ __nv_bfloat16 g_wt2o_lo[(size_t)HH * HH];
__device__ __nv_bfloat16 g_wt3o_hi[(size_t)OPAD * HH];
__device__ __nv_bfloat16 g_wt3o_lo[(size_t)OPAD * HH];
__device__ __nv_bfloat16 g_wt1a_hi[(size_t)HH * DD];
__device__ __nv_bfloat16 g_wt1a_lo[(size_t)HH * DD];
__device__ __nv_bfloat16 g_wt2a_hi[(size_t)HH * HH];
__device__ __nv_bfloat16 g_wt2a_lo[(size_t)HH * HH];
__device__ __nv_bfloat16 g_wt3a_hi[(size_t)APAD * HH];
__device__ __nv_bfloat16 g_wt3a_lo[(size_t)APAD * HH];
__device__ float g_lo[(size_t)MM * OO];
__device__ float g_la[(size_t)MM * AAd];
__device__ float2 g_st_o[MM];
__device__ float2 g_st_a[MM];
__device__ int   g_rowmap[MM];
__device__ int   g_rowstart[BB];
__device__ int   g_Meff;
__device__ int   g_desc[LL];

// ---------------- PTX helpers (baseline sm_80+ features only) ----------------
__device__ __forceinline__ uint32_t smem_u32_of(const void* p) {
    uint32_t a;
    asm("{ .reg .u64 t; cvta.to.shared.u64 t, %1; cvt.u32.u64 %0, t; }" : "=r"(a) : "l"(p));
    return a;
}
__device__ __forceinline__ void cp16(uint32_t dst, const void* src) {
    asm volatile("cp.async.cg.shared.global [%0], [%1], 16;" :: "r"(dst), "l"(src) : "memory");
}
__device__ __forceinline__ void cp_commit() {
    asm volatile("cp.async.commit_group;" ::: "memory");
}
template<int N>
__device__ __forceinline__ void cp_wait() {
    asm volatile("cp.async.wait_group %0;" :: "n"(N) : "memory");
}
__device__ __forceinline__ void ldsm4(uint32_t* r, uint32_t addr) {
    asm volatile("ldmatrix.sync.aligned.m8n8.x4.shared.b16 {%0,%1,%2,%3}, [%4];"
        : "=r"(r[0]), "=r"(r[1]), "=r"(r[2]), "=r"(r[3]) : "r"(addr));
}
__device__ __forceinline__ void mma16816(float* c, const uint32_t* a, const uint32_t* b) {
    asm volatile("mma.sync.aligned.m16n8k16.row.col.f32.bf16.bf16.f32 "
        "{%0,%1,%2,%3}, {%4,%5,%6,%7}, {%8,%9}, {%0,%1,%2,%3};"
        : "+f"(c[0]), "+f"(c[1]), "+f"(c[2]), "+f"(c[3])
        : "r"(a[0]), "r"(a[1]), "r"(a[2]), "r"(a[3]), "r"(b[0]), "r"(b[1]));
}

// ---------------- setup: live-row compaction ----------------
__global__ void setup_kernel(const int* __restrict__ num_descs) {
    __shared__ int cnt[BB];
    int b = threadIdx.x;
    int c = num_descs[b];
    if (c < 1) c = 1;
    cnt[b] = c;
    __syncthreads();
    if (b == 0) {
        int acc = 0;
        for (int i = 0; i < BB; i++) { g_rowstart[i] = acc; acc += cnt[i]; }
        g_Meff = acc;
    }
    __syncthreads();
    int start = g_rowstart[b];
    for (int i = 0; i < c; i++) g_rowmap[start + i] = b * NN + i;
}

// ---------------- x compaction + bf16 hi/lo split ----------------
__global__ void xsplit_kernel(const float* __restrict__ x) {
    int r = blockIdx.x;
    int Meff = g_Meff;
    int mceil = (Meff + 127) & ~127;
    if (r >= mceil) return;
    int src = g_rowmap[r < Meff ? r : (Meff - 1)];
    const float4* xp = (const float4*)(x + (size_t)src * DD);
    uint32_t* dh = (uint32_t*)(g_xc_hi + (size_t)r * DD);
    uint32_t* dl = (uint32_t*)(g_xc_lo + (size_t)r * DD);
    for (int i = threadIdx.x; i < DD / 4; i += 256) {
        float4 v = xp[i];
        __nv_bfloat16 h0 = __float2bfloat16(v.x);
        __nv_bfloat16 h1 = __float2bfloat16(v.y);
        __nv_bfloat16 h2 = __float2bfloat16(v.z);
        __nv_bfloat16 h3 = __float2bfloat16(v.w);
        __nv_bfloat16 l0 = __float2bfloat16(v.x - __bfloat162float(h0));
        __nv_bfloat16 l1 = __float2bfloat16(v.y - __bfloat162float(h1));
        __nv_bfloat16 l2 = __float2bfloat16(v.z - __bfloat162float(h2));
        __nv_bfloat16 l3 = __float2bfloat16(v.w - __bfloat162float(h3));
        __nv_bfloat162 ph0; ph0.x = h0; ph0.y = h1;
        __nv_bfloat162 ph1; ph1.x = h2; ph1.y = h3;
        __nv_bfloat162 pl0; pl0.x = l0; pl0.y = l1;
        __nv_bfloat162 pl1; pl1.x = l2; pl1.y = l3;
        dh[2*i]   = *(uint32_t*)&ph0;
        dh[2*i+1] = *(uint32_t*)&ph1;
        dl[2*i]   = *(uint32_t*)&pl0;
        dl[2*i+1] = *(uint32_t*)&pl1;
    }
}

// ---------------- weight transpose + split (2 slots via z), zero-pads ----------------
// Per z: W, dest, N, padded extent (x-blocks beyond pad exit).
__global__ void wsplit2_kernel(const float* __restrict__ W0, const float* __restrict__ W1,
                               __nv_bfloat16* T0h, __nv_bfloat16* T0l,
                               __nv_bfloat16* T1h, __nv_bfloat16* T1l,
                               int K, int N0, int N1, int NP0, int NP1) {
    const float* W = blockIdx.z ? W1 : W0;
    __nv_bfloat16* Th = blockIdx.z ? T1h : T0h;
    __nv_bfloat16* Tl = blockIdx.z ? T1l : T0l;
    const int N  = blockIdx.z ? N1  : N0;
    const int NP = blockIdx.z ? NP1 : NP0;
    int n0 = blockIdx.x * 32, k0 = blockIdx.y * 32;
    if (n0 >= NP) return;
    __shared__ float t[32][33];
    int tx = threadIdx.x, ty = threadIdx.y;
    for (int i = ty; i < 32; i += 8) {
        int n = n0 + tx;
        t[i][tx] = (n < N) ? W[(size_t)(k0 + i) * N + n] : 0.f;
    }
    __syncthreads();
    for (int i = ty; i < 32; i += 8) {
        int n = n0 + i;
        float v = t[tx][i];
        __nv_bfloat16 h = __float2bfloat16(v);
        Th[(size_t)n * K + k0 + tx] = h;
        Tl[(size_t)n * K + k0 + tx] = __float2bfloat16(v - __bfloat162float(h));
    }
}

// ---------------- HMMA split-bf16 GEMM (8 warps of 64x64) ----------------
// Block tile 128x256, 256 threads = 8 warps (2M x 4N) of 64x64 each.
// K-chunk 64, 2-stage cp.async, two barriers per chunk (best measured config).
#define STG_BYTES 98304u
#define GEMM_SMEM (2 * 98304)
#define OFF_AL 16384u
#define OFF_BH 32768u
#define OFF_BL 65536u

struct GArgs {
    const __nv_bfloat16 *Ahi0, *Alo0, *Bhi0, *Blo0;
    const __nv_bfloat16 *Ahi1, *Alo1, *Bhi1, *Blo1;
    const float *bias0, *bias1;
    float *Cf0, *Cf1;
    __nv_bfloat16 *Chi0, *Clo0, *Chi1, *Clo1;
    int N0, N1, K;
};

// 128 rows x 64 cols bf16 -> swizzled smem (256 threads, 4 chunks each)
__device__ __forceinline__ void load_tile128(const __nv_bfloat16* __restrict__ g,
                                             int rowStride, int row0, int k0,
                                             uint32_t sdst, int tid) {
    #pragma unroll
    for (int it = 0; it < 4; it++) {
        int v = tid + it * 256;
        int r = v >> 3, cv = v & 7;
        const void* src = g + (size_t)(row0 + r) * rowStride + k0 + cv * 8;
        uint32_t cb = (uint32_t)(cv * 16);
        uint32_t sw = (uint32_t)(r * 128) + (cb ^ (((uint32_t)r & 7u) << 4));
        cp16(sdst + sw, src);
    }
}
// 256 rows x 64 cols bf16 (8 chunks each)
__device__ __forceinline__ void load_tile256(const __nv_bfloat16* __restrict__ g,
                                             int rowStride, int row0, int k0,
                                             uint32_t sdst, int tid) {
    #pragma unroll
    for (int it = 0; it < 8; it++) {
        int v = tid + it * 256;
        int r = v >> 3, cv = v & 7;
        const void* src = g + (size_t)(row0 + r) * rowStride + k0 + cv * 8;
        uint32_t cb = (uint32_t)(cv * 16);
        uint32_t sw = (uint32_t)(r * 128) + (cb ^ (((uint32_t)r & 7u) << 4));
        cp16(sdst + sw, src);
    }
}

__device__ __forceinline__ uint32_t swaddr(uint32_t base, int row, int cb) {
    return base + (uint32_t)(row * 128) + (((uint32_t)cb) ^ (((uint32_t)row & 7u) << 4));
}

// OUTMODE 0: relu + bf16 hi/lo outputs.  OUTMODE 1: fp32 outputs, no relu.
template<int OUTMODE>
__global__ __launch_bounds__(256, 1)
void hgemm(GArgs g)
{
    const int Meff = g_Meff;
    const int rowBase = blockIdx.y * 128;
    if (rowBase >= Meff) return;
    const int z = blockIdx.z;
    const int N = z ? g.N1 : g.N0;
    const int colBase = blockIdx.x * 256;
    if (colBase >= ((N + 255) & ~255)) return;

    const int tid = threadIdx.x;
    const __nv_bfloat16* Ahi = z ? g.Ahi1 : g.Ahi0;
    const __nv_bfloat16* Alo = z ? g.Alo1 : g.Alo0;
    const __nv_bfloat16* Bhi = z ? g.Bhi1 : g.Bhi0;
    const __nv_bfloat16* Blo = z ? g.Blo1 : g.Blo0;
    const float* bias        = z ? g.bias1 : g.bias0;
    float* Cf                = z ? g.Cf1 : g.Cf0;
    __nv_bfloat16* Chi       = z ? g.Chi1 : g.Chi0;
    __nv_bfloat16* Clo       = z ? g.Clo1 : g.Clo0;
    const int K = g.K;

    extern __shared__ char smem[];
    const uint32_t sbase = smem_u32_of(smem);

    const int warp = tid >> 5, lane = tid & 31;
    const int wm = (warp >> 2) * 64;      // 0 / 64
    const int wn = (warp & 3) * 64;       // 0 / 64 / 128 / 192

    float acc[4][8][4];
    #pragma unroll
    for (int i = 0; i < 4; i++)
        #pragma unroll
        for (int j = 0; j < 8; j++)
            #pragma unroll
            for (int c = 0; c < 4; c++) acc[i][j][c] = 0.f;

    const int nk = K >> 6;

    #pragma unroll
    for (int p = 0; p < 2; p++) {
        uint32_t st = sbase + (uint32_t)p * STG_BYTES;
        load_tile128(Ahi, K, rowBase, p * 64, st,          tid);
        load_tile128(Alo, K, rowBase, p * 64, st + OFF_AL, tid);
        load_tile256(Bhi, K, colBase, p * 64, st + OFF_BH, tid);
        load_tile256(Blo, K, colBase, p * 64, st + OFF_BL, tid);
        cp_commit();
    }

    const int aRowL = wm + (lane & 15);
    const int aSel  = (lane >> 4);
    const int bRowL = wn + (lane & 7) + ((lane >> 4) << 3);
    const int bSel  = (lane >> 3) & 1;

    for (int i = 0; i < nk; i++) {
        if (i == nk - 1) cp_wait<0>(); else cp_wait<1>();
        __syncthreads();

        const uint32_t sA  = sbase + (uint32_t)(i & 1) * STG_BYTES;
        const uint32_t sAl = sA + OFF_AL;
        const uint32_t sBh = sA + OFF_BH;
        const uint32_t sBl = sA + OFF_BL;

        #pragma unroll
        for (int kk = 0; kk < 4; kk++) {
            const int aCb = kk * 32 + aSel * 16;
            const int bCb = kk * 32 + bSel * 16;

            uint32_t af[16], bhf[16], blf[16];
            #pragma unroll
            for (int mi = 0; mi < 4; mi++)
                ldsm4(&af[mi * 4], swaddr(sA, aRowL + mi * 16, aCb));
            #pragma unroll
            for (int p = 0; p < 4; p++) {
                ldsm4(&bhf[p * 4], swaddr(sBh, bRowL + p * 16, bCb));
                ldsm4(&blf[p * 4], swaddr(sBl, bRowL + p * 16, bCb));
            }
            // hi*hi and hi*lo
            #pragma unroll
            for (int mi = 0; mi < 4; mi++)
                #pragma unroll
                for (int ni = 0; ni < 8; ni++) {
                    mma16816(acc[mi][ni], &af[mi * 4], &bhf[ni * 2]);
                    mma16816(acc[mi][ni], &af[mi * 4], &blf[ni * 2]);
                }
            // lo*hi
            #pragma unroll
            for (int mi = 0; mi < 4; mi++)
                ldsm4(&af[mi * 4], swaddr(sAl, aRowL + mi * 16, aCb));
            #pragma unroll
            for (int mi = 0; mi < 4; mi++)
                #pragma unroll
                for (int ni = 0; ni < 8; ni++)
                    mma16816(acc[mi][ni], &af[mi * 4], &bhf[ni * 2]);
        }

        if (i + 2 < nk) {
            __syncthreads();
            const int k0 = (i + 2) << 6;
            uint32_t st = sbase + (uint32_t)(i & 1) * STG_BYTES;
            load_tile128(Ahi, K, rowBase, k0, st,          tid);
            load_tile128(Alo, K, rowBase, k0, st + OFF_AL, tid);
            load_tile256(Bhi, K, colBase, k0, st + OFF_BH, tid);
            load_tile256(Blo, K, colBase, k0, st + OFF_BL, tid);
            cp_commit();
        }
    }

    // epilogue
    #pragma unroll
    for (int mi = 0; mi < 4; mi++) {
        #pragma unroll
        for (int ni = 0; ni < 8; ni++) {
            const int col = colBase + wn + ni * 8 + (lane & 3) * 2;
            if (col < N) {
                const float2 bv = *(const float2*)(bias + col);
                #pragma unroll
                for (int h = 0; h < 2; h++) {
                    const int row = rowBase + wm + mi * 16 + (lane >> 2) + h * 8;
                    float v0 = acc[mi][ni][h * 2 + 0] + bv.x;
                    float v1 = acc[mi][ni][h * 2 + 1] + bv.y;
                    if (OUTMODE == 0) {
                        v0 = fmaxf(v0, 0.f);
                        v1 = fmaxf(v1, 0.f);
                        __nv_bfloat16 h0 = __float2bfloat16(v0);
                        __nv_bfloat16 h1 = __float2bfloat16(v1);
                        __nv_bfloat16 l0 = __float2bfloat16(v0 - __bfloat162float(h0));
                        __nv_bfloat16 l1 = __float2bfloat16(v1 - __bfloat162float(h1));
                        __nv_bfloat162 ph; ph.x = h0; ph.y = h1;
                        __nv_bfloat162 pl; pl.x = l0; pl.y = l1;
                        *(uint32_t*)(Chi + (size_t)row * N + col) = *(uint32_t*)&ph;
                        *(uint32_t*)(Clo + (size_t)row * N + col) = *(uint32_t*)&pl;
                    } else {
                        float2 v; v.x = v0; v.y = v1;
                        *(float2*)(Cf + (size_t)row * N + col) = v;
                    }
                }
            }
        }
    }
}

// ---------------- per-row softmax stats (both branches, y = branch), float4 ----------------
__global__ void rowstats2_kernel(const float* __restrict__ lg0, const float* __restrict__ lg1,
                                 float2* __restrict__ st0, float2* __restrict__ st1,
                                 int nc0, int nc1)
{
    int r = blockIdx.x;
    if (r >= g_Meff) return;
    const float* p = blockIdx.y ? lg1 : lg0;
    float2* stats  = blockIdx.y ? st1 : st0;
    const int ncols = blockIdx.y ? nc1 : nc0;
    const float4* p4 = (const float4*)(p + (size_t)r * ncols);
    const int nv = ncols >> 2;       // 400 or 100
    const int tid = threadIdx.x;     // 128
    __shared__ float red[128];

    float mx = -3.402823466e38f;
    for (int j = tid; j < nv; j += 128) {
        float4 v = p4[j];
        mx = fmaxf(mx, fmaxf(fmaxf(v.x, v.y), fmaxf(v.z, v.w)));
    }
    red[tid] = mx; __syncthreads();
    for (int s = 64; s; s >>= 1) {
        if (tid < s) red[tid] = fmaxf(red[tid], red[tid + s]);
        __syncthreads();
    }
    mx = red[0]; __syncthreads();

    float sum = 0.f;
    for (int j = tid; j < nv; j += 128) {
        float4 v = p4[j];
        sum += expf(v.x - mx) + expf(v.y - mx) + expf(v.z - mx) + expf(v.w - mx);
    }
    red[tid] = sum; __syncthreads();
    for (int s = 64; s; s >>= 1) {
        if (tid < s) red[tid] += red[tid + s];
        __syncthreads();
    }
    if (tid == 0) stats[r] = make_float2(mx, red[0]);
}

// ---------------- score + argmax: one warp per label row ----------------
__global__ void score_kernel(const int* __restrict__ label_img,
                             const int* __restrict__ obj_labels,
                             const int* __restrict__ att_labels,
                             const int* __restrict__ num_descs)
{
    int l = blockIdx.x * 8 + (threadIdx.x >> 5);
    int lane = threadIdx.x & 31;
    if (l >= LL) return;
    int b  = label_img[l];
    int nd = num_descs[b];
    int oj = obj_labels[l];
    int aj = att_labels[l];
    int rs = g_rowstart[b];

    float best = -1.0f;
    int   bidx = 0;
    for (int n = lane; n < nd; n += 32) {
        int r = rs + n;
        float2 so = g_st_o[r];
        float2 sa = g_st_a[r];
        float po = expf(g_lo[(size_t)r * OO  + oj] - so.x) / so.y;
        float pa = expf(g_la[(size_t)r * AAd + aj] - sa.x) / sa.y;
        float s = po * pa;
        if (s > best) { best = s; bidx = n; }
    }
    #pragma unroll
    for (int off = 16; off; off >>= 1) {
        float ob = __shfl_down_sync(0xffffffffu, best, off);
        int   oi = __shfl_down_sync(0xffffffffu, bidx, off);
        if (ob > best || (ob == best && oi < bidx)) { best = ob; bidx = oi; }
    }
    if (lane == 0) g_desc[l] = bidx;
}

// ---------------- final gather: softmax of the selected row (float4) ----------------
__global__ void gather_kernel(const int* __restrict__ label_img,
                              float* __restrict__ out)
{
    int l = blockIdx.x;
    int b = label_img[l];
    int r = g_rowstart[b] + g_desc[l];

    float2 so = g_st_o[r];
    float inv_o = 1.0f / so.y;
    const float4* lo4 = (const float4*)(g_lo + (size_t)r * OO);
    float4* oo4 = (float4*)(out + (size_t)l * OO);
    for (int j = threadIdx.x; j < OO / 4; j += blockDim.x) {
        float4 v = lo4[j];
        float4 w;
        w.x = expf(v.x - so.x) * inv_o;
        w.y = expf(v.y - so.x) * inv_o;
        w.z = expf(v.z - so.x) * inv_o;
        w.w = expf(v.w - so.x) * inv_o;
        oo4[j] = w;
    }

    float2 sa = g_st_a[r];
    float inv_a = 1.0f / sa.y;
    const float4* la4 = (const float4*)(g_la + (size_t)r * AAd);
    float4* oa4 = (float4*)(out + (size_t)LL * OO + (size_t)l * AAd);
    for (int j = threadIdx.x; j < AAd / 4; j += blockDim.x) {
        float4 v = la4[j];
        float4 w;
        w.x = expf(v.x - sa.x) * inv_a;
        w.y = expf(v.y - sa.x) * inv_a;
        w.z = expf(v.z - sa.x) * inv_a;
        w.w = expf(v.w - sa.x) * inv_a;
        oa4[j] = w;
    }
}

// ---------------- launch ----------------
extern "C" void kernel_launch(void* const* d_in, const int* in_sizes, int n_in,
                              void* d_out, int out_size)
{
    const float* x          = (const float*)d_in[0];
    const int*   num_descs  = (const int*)  d_in[1];
    const int*   label_img  = (const int*)  d_in[2];
    const int*   obj_labels = (const int*)  d_in[3];
    const int*   att_labels = (const int*)  d_in[4];
    const float* w1o = (const float*)d_in[5];
    const float* b1o = (const float*)d_in[6];
    const float* w2o = (const float*)d_in[7];
    const float* b2o = (const float*)d_in[8];
    const float* w3o = (const float*)d_in[9];
    const float* b3o = (const float*)d_in[10];
    const float* w1a = (const float*)d_in[11];
    const float* b1a = (const float*)d_in[12];
    const float* w2a = (const float*)d_in[13];
    const float* b2a = (const float*)d_in[14];
    const float* w3a = (const float*)d_in[15];
    const float* b3a = (const float*)d_in[16];
    float* out = (float*)d_out;

    __nv_bfloat16 *xch, *xcl;
    __nv_bfloat16 *h1oh, *h1ol, *h1ah, *h1al, *h2oh, *h2ol, *h2ah, *h2al;
    __nv_bfloat16 *w1oh, *w1ol, *w2oh, *w2ol, *w3oh, *w3ol;
    __nv_bfloat16 *w1ah, *w1al, *w2ah, *w2al, *w3ah, *w3al;
    float *lo, *la;
    float2 *sto, *sta;
    cudaGetSymbolAddress((void**)&xch, g_xc_hi);   cudaGetSymbolAddress((void**)&xcl, g_xc_lo);
    cudaGetSymbolAddress((void**)&h1oh, g_h1o_hi); cudaGetSymbolAddress((void**)&h1ol, g_h1o_lo);
    cudaGetSymbolAddress((void**)&h1ah, g_h1a_hi); cudaGetSymbolAddress((void**)&h1al, g_h1a_lo);
    cudaGetSymbolAddress((void**)&h2oh, g_h2o_hi); cudaGetSymbolAddress((void**)&h2ol, g_h2o_lo);
    cudaGetSymbolAddress((void**)&h2ah, g_h2a_hi); cudaGetSymbolAddress((void**)&h2al, g_h2a_lo);
    cudaGetSymbolAddress((void**)&w1oh, g_wt1o_hi); cudaGetSymbolAddress((void**)&w1ol, g_wt1o_lo);
    cudaGetSymbolAddress((void**)&w2oh, g_wt2o_hi); cudaGetSymbolAddress((void**)&w2ol, g_wt2o_lo);
    cudaGetSymbolAddress((void**)&w3oh, g_wt3o_hi); cudaGetSymbolAddress((void**)&w3ol, g_wt3o_lo);
    cudaGetSymbolAddress((void**)&w1ah, g_wt1a_hi); cudaGetSymbolAddress((void**)&w1al, g_wt1a_lo);
    cudaGetSymbolAddress((void**)&w2ah, g_wt2a_hi); cudaGetSymbolAddress((void**)&w2al, g_wt2a_lo);
    cudaGetSymbolAddress((void**)&w3ah, g_wt3a_hi); cudaGetSymbolAddress((void**)&w3al, g_wt3a_lo);
    cudaGetSymbolAddress((void**)&lo,  g_lo);
    cudaGetSymbolAddress((void**)&la,  g_la);
    cudaGetSymbolAddress((void**)&sto, g_st_o);
    cudaGetSymbolAddress((void**)&sta, g_st_a);

    cudaFuncSetAttribute(hgemm<0>, cudaFuncAttributeMaxDynamicSharedMemorySize, GEMM_SMEM);
    cudaFuncSetAttribute(hgemm<1>, cudaFuncAttributeMaxDynamicSharedMemorySize, GEMM_SMEM);

    const int MT = MM / 128;  // 100 M tiles max; blocks past g_Meff exit
    dim3 wb(32, 8);

    // 1
    setup_kernel<<<1, BB>>>(num_descs);
    // 2
    xsplit_kernel<<<MM, 256>>>(x);
    // 3: w1 prep, both branches
    wsplit2_kernel<<<dim3(HH/32, DD/32, 2), wb>>>(w1o, w1a, w1oh, w1ol, w1ah, w1al, DD, HH, HH, HH, HH);
    // 4: layer-1 GEMM (profiled by ncu)
    GArgs a1 = { xch, xcl, w1oh, w1ol,
                 xch, xcl, w1ah, w1al,
                 b1o, b1a, nullptr, nullptr,
                 h1oh, h1ol, h1ah, h1al, HH, HH, DD };
    hgemm<0><<<dim3(HH/256, MT, 2), 256, GEMM_SMEM>>>(a1);
    // 5
    wsplit2_kernel<<<dim3(HH/32, HH/32, 2), wb>>>(w2o, w2a, w2oh, w2ol, w2ah, w2al, HH, HH, HH, HH, HH);
    // 6: layer-2 GEMM
    GArgs a2 = { h1oh, h1ol, w2oh, w2ol,
                 h1ah, h1al, w2ah, w2al,
                 b2o, b2a, nullptr, nullptr,
                 h2oh, h2ol, h2ah, h2al, HH, HH, HH };
    hgemm<0><<<dim3(HH/256, MT, 2), 256, GEMM_SMEM>>>(a2);
    // 7: w3 prep, both branches in one launch (pads zeroed; att blocks past APAD exit)
    wsplit2_kernel<<<dim3(OPAD/32, HH/32, 2), wb>>>(w3o, w3a, w3oh, w3ol, w3ah, w3al, HH, OO, AAd, OPAD, APAD);
    // 8: layer-3, both branches merged (z=0 obj N=OO, z=1 att N=AAd)
    GArgs a3 = { h2oh, h2ol, w3oh, w3ol,
                 h2ah, h2al, w3ah, w3al,
                 b3o, b3a, lo, la,
                 nullptr, nullptr, nullptr, nullptr, OO, AAd, HH };
    hgemm<1><<<dim3(OPAD/256, MT, 2), 256, GEMM_SMEM>>>(a3);

    rowstats2_kernel<<<dim3(MM, 2), 128>>>(lo, la, sto, sta, OO, AAd);
    score_kernel<<<(LL + 7) / 8, 256>>>(label_img, obj_labels, att_labels, num_descs);
    gather_kernel<<<LL, 256>>>(label_img, out);
}

// round 15
// speedup vs baseline: 1.5361x; 1.0004x over previous
#include <cuda_runtime.h>
#include <cuda_bf16.h>
#include <math.h>
#include <stdint.h>

// Problem constants
#define BB 128
#define NN 100
#define DD 2048
#define HH 1024
#define OO 1600
#define AAd 400
#define LL 2048
#define MM (BB*NN)   // 12800

#define OPAD 1792    // OO padded to 256
#define APAD 512     // AAd padded to 256

// ---------------- device scratch (no allocs allowed) ----------------
__device__ __nv_bfloat16 g_xc_hi[(size_t)MM * DD];
__device__ __nv_bfloat16 g_xc_lo[(size_t)MM * DD];
__device__ __nv_bfloat16 g_h1o_hi[(size_t)MM * HH];
__device__ __nv_bfloat16 g_h1o_lo[(size_t)MM * HH];
__device__ __nv_bfloat16 g_h1a_hi[(size_t)MM * HH];
__device__ __nv_bfloat16 g_h1a_lo[(size_t)MM * HH];
__device__ __nv_bfloat16 g_h2o_hi[(size_t)MM * HH];
__device__ __nv_bfloat16 g_h2o_lo[(size_t)MM * HH];
__device__ __nv_bfloat16 g_h2a_hi[(size_t)MM * HH];
__device__ __nv_bfloat16 g_h2a_lo[(size_t)MM * HH];
__device__ __nv_bfloat16 g_wt1o_hi[(size_t)HH * DD];
__device__ __nv_bfloat16 g_wt1o_lo[(size_t)HH * DD];
__device__ __nv_bfloat16 g_wt2o_hi[(size_t)HH * HH];
__device__ __nv_bfloat16 g_wt2o_lo[(size_t)HH * HH];
__device__ __nv_bfloat16 g_wt3o_hi[(size_t)OPAD * HH];
__device__ __nv_bfloat16 g_wt3o_lo[(size_t)OPAD * HH];
__device__ __nv_bfloat16 g_wt1a_hi[(size_t)HH * DD];
__device__ __nv_bfloat16 g_wt1a_lo[(size_t)HH * DD];
__device__ __nv_bfloat16 g_wt2a_hi[(size_t)HH * HH];
__device__ __nv_bfloat16 g_wt2a_lo[(size_t)HH * HH];
__device__ __nv_bfloat16 g_wt3a_hi[(size_t)APAD * HH];
__device__ __nv_bfloat16 g_wt3a_lo[(size_t)APAD * HH];
__device__ float g_lo[(size_t)MM * OO];
__device__ float g_la[(size_t)MM * AAd];
__device__ float2 g_st_o[MM];
__device__ float2 g_st_a[MM];
__device__ int   g_rowmap[MM];
__device__ int   g_rowstart[BB];
__device__ int   g_Meff;

// ---------------- PTX helpers (baseline sm_80+ features only) ----------------
__device__ __forceinline__ uint32_t smem_u32_of(const void* p) {
    uint32_t a;
    asm("{ .reg .u64 t; cvta.to.shared.u64 t, %1; cvt.u32.u64 %0, t; }" : "=r"(a) : "l"(p));
    return a;
}
__device__ __forceinline__ void cp16(uint32_t dst, const void* src) {
    asm volatile("cp.async.cg.shared.global [%0], [%1], 16;" :: "r"(dst), "l"(src) : "memory");
}
__device__ __forceinline__ void cp_commit() {
    asm volatile("cp.async.commit_group;" ::: "memory");
}
template<int N>
__device__ __forceinline__ void cp_wait() {
    asm volatile("cp.async.wait_group %0;" :: "n"(N) : "memory");
}
__device__ __forceinline__ void ldsm4(uint32_t* r, uint32_t addr) {
    asm volatile("ldmatrix.sync.aligned.m8n8.x4.shared.b16 {%0,%1,%2,%3}, [%4];"
        : "=r"(r[0]), "=r"(r[1]), "=r"(r[2]), "=r"(r[3]) : "r"(addr));
}
__device__ __forceinline__ void mma16816(float* c, const uint32_t* a, const uint32_t* b) {
    asm volatile("mma.sync.aligned.m16n8k16.row.col.f32.bf16.bf16.f32 "
        "{%0,%1,%2,%3}, {%4,%5,%6,%7}, {%8,%9}, {%0,%1,%2,%3};"
        : "+f"(c[0]), "+f"(c[1]), "+f"(c[2]), "+f"(c[3])
        : "r"(a[0]), "r"(a[1]), "r"(a[2]), "r"(a[3]), "r"(b[0]), "r"(b[1]));
}

// ---------------- setup: live-row compaction ----------------
__global__ void setup_kernel(const int* __restrict__ num_descs) {
    __shared__ int cnt[BB];
    int b = threadIdx.x;
    int c = num_descs[b];
    if (c < 1) c = 1;
    cnt[b] = c;
    __syncthreads();
    if (b == 0) {
        int acc = 0;
        for (int i = 0; i < BB; i++) { g_rowstart[i] = acc; acc += cnt[i]; }
        g_Meff = acc;
    }
    __syncthreads();
    int start = g_rowstart[b];
    for (int i = 0; i < c; i++) g_rowmap[start + i] = b * NN + i;
}

// ---------------- x compaction + bf16 hi/lo split ----------------
__global__ void xsplit_kernel(const float* __restrict__ x) {
    int r = blockIdx.x;
    int Meff = g_Meff;
    int mceil = (Meff + 127) & ~127;
    if (r >= mceil) return;
    int src = g_rowmap[r < Meff ? r : (Meff - 1)];
    const float4* xp = (const float4*)(x + (size_t)src * DD);
    uint32_t* dh = (uint32_t*)(g_xc_hi + (size_t)r * DD);
    uint32_t* dl = (uint32_t*)(g_xc_lo + (size_t)r * DD);
    for (int i = threadIdx.x; i < DD / 4; i += 256) {
        float4 v = xp[i];
        __nv_bfloat16 h0 = __float2bfloat16(v.x);
        __nv_bfloat16 h1 = __float2bfloat16(v.y);
        __nv_bfloat16 h2 = __float2bfloat16(v.z);
        __nv_bfloat16 h3 = __float2bfloat16(v.w);
        __nv_bfloat16 l0 = __float2bfloat16(v.x - __bfloat162float(h0));
        __nv_bfloat16 l1 = __float2bfloat16(v.y - __bfloat162float(h1));
        __nv_bfloat16 l2 = __float2bfloat16(v.z - __bfloat162float(h2));
        __nv_bfloat16 l3 = __float2bfloat16(v.w - __bfloat162float(h3));
        __nv_bfloat162 ph0; ph0.x = h0; ph0.y = h1;
        __nv_bfloat162 ph1; ph1.x = h2; ph1.y = h3;
        __nv_bfloat162 pl0; pl0.x = l0; pl0.y = l1;
        __nv_bfloat162 pl1; pl1.x = l2; pl1.y = l3;
        dh[2*i]   = *(uint32_t*)&ph0;
        dh[2*i+1] = *(uint32_t*)&ph1;
        dl[2*i]   = *(uint32_t*)&pl0;
        dl[2*i+1] = *(uint32_t*)&pl1;
    }
}

// ---------------- weight transpose + split (2 slots via z), zero-pads ----------------
__global__ void wsplit2_kernel(const float* __restrict__ W0, const float* __restrict__ W1,
                               __nv_bfloat16* T0h, __nv_bfloat16* T0l,
                               __nv_bfloat16* T1h, __nv_bfloat16* T1l,
                               int K, int N0, int N1, int NP0, int NP1) {
    const float* W = blockIdx.z ? W1 : W0;
    __nv_bfloat16* Th = blockIdx.z ? T1h : T0h;
    __nv_bfloat16* Tl = blockIdx.z ? T1l : T0l;
    const int N  = blockIdx.z ? N1  : N0;
    const int NP = blockIdx.z ? NP1 : NP0;
    int n0 = blockIdx.x * 32, k0 = blockIdx.y * 32;
    if (n0 >= NP) return;
    __shared__ float t[32][33];
    int tx = threadIdx.x, ty = threadIdx.y;
    for (int i = ty; i < 32; i += 8) {
        int n = n0 + tx;
        t[i][tx] = (n < N) ? W[(size_t)(k0 + i) * N + n] : 0.f;
    }
    __syncthreads();
    for (int i = ty; i < 32; i += 8) {
        int n = n0 + i;
        float v = t[tx][i];
        __nv_bfloat16 h = __float2bfloat16(v);
        Th[(size_t)n * K + k0 + tx] = h;
        Tl[(size_t)n * K + k0 + tx] = __float2bfloat16(v - __bfloat162float(h));
    }
}

// ---------------- HMMA split-bf16 GEMM (8 warps of 64x64) ----------------
// Block tile 128x256, 256 threads = 8 warps (2M x 4N) of 64x64 each.
// K-chunk 64, 2-stage cp.async, two barriers per chunk (best measured config).
#define STG_BYTES 98304u
#define GEMM_SMEM (2 * 98304)
#define OFF_AL 16384u
#define OFF_BH 32768u
#define OFF_BL 65536u

struct GArgs {
    const __nv_bfloat16 *Ahi0, *Alo0, *Bhi0, *Blo0;
    const __nv_bfloat16 *Ahi1, *Alo1, *Bhi1, *Blo1;
    const float *bias0, *bias1;
    float *Cf0, *Cf1;
    __nv_bfloat16 *Chi0, *Clo0, *Chi1, *Clo1;
    int N0, N1, K;
};

// 128 rows x 64 cols bf16 -> swizzled smem (256 threads, 4 chunks each)
__device__ __forceinline__ void load_tile128(const __nv_bfloat16* __restrict__ g,
                                             int rowStride, int row0, int k0,
                                             uint32_t sdst, int tid) {
    #pragma unroll
    for (int it = 0; it < 4; it++) {
        int v = tid + it * 256;
        int r = v >> 3, cv = v & 7;
        const void* src = g + (size_t)(row0 + r) * rowStride + k0 + cv * 8;
        uint32_t cb = (uint32_t)(cv * 16);
        uint32_t sw = (uint32_t)(r * 128) + (cb ^ (((uint32_t)r & 7u) << 4));
        cp16(sdst + sw, src);
    }
}
// 256 rows x 64 cols bf16 (8 chunks each)
__device__ __forceinline__ void load_tile256(const __nv_bfloat16* __restrict__ g,
                                             int rowStride, int row0, int k0,
                                             uint32_t sdst, int tid) {
    #pragma unroll
    for (int it = 0; it < 8; it++) {
        int v = tid + it * 256;
        int r = v >> 3, cv = v & 7;
        const void* src = g + (size_t)(row0 + r) * rowStride + k0 + cv * 8;
        uint32_t cb = (uint32_t)(cv * 16);
        uint32_t sw = (uint32_t)(r * 128) + (cb ^ (((uint32_t)r & 7u) << 4));
        cp16(sdst + sw, src);
    }
}

__device__ __forceinline__ uint32_t swaddr(uint32_t base, int row, int cb) {
    return base + (uint32_t)(row * 128) + (((uint32_t)cb) ^ (((uint32_t)row & 7u) << 4));
}

// OUTMODE 0: relu + bf16 hi/lo outputs.  OUTMODE 1: fp32 outputs, no relu.
template<int OUTMODE>
__global__ __launch_bounds__(256, 1)
void hgemm(GArgs g)
{
    const int Meff = g_Meff;
    const int rowBase = blockIdx.y * 128;
    if (rowBase >= Meff) return;
    const int z = blockIdx.z;
    const int N = z ? g.N1 : g.N0;
    const int colBase = blockIdx.x * 256;
    if (colBase >= ((N + 255) & ~255)) return;

    const int tid = threadIdx.x;
    const __nv_bfloat16* Ahi = z ? g.Ahi1 : g.Ahi0;
    const __nv_bfloat16* Alo = z ? g.Alo1 : g.Alo0;
    const __nv_bfloat16* Bhi = z ? g.Bhi1 : g.Bhi0;
    const __nv_bfloat16* Blo = z ? g.Blo1 : g.Blo0;
    const float* bias        = z ? g.bias1 : g.bias0;
    float* Cf                = z ? g.Cf1 : g.Cf0;
    __nv_bfloat16* Chi       = z ? g.Chi1 : g.Chi0;
    __nv_bfloat16* Clo       = z ? g.Clo1 : g.Clo0;
    const int K = g.K;

    extern __shared__ char smem[];
    const uint32_t sbase = smem_u32_of(smem);

    const int warp = tid >> 5, lane = tid & 31;
    const int wm = (warp >> 2) * 64;      // 0 / 64
    const int wn = (warp & 3) * 64;       // 0 / 64 / 128 / 192

    float acc[4][8][4];
    #pragma unroll
    for (int i = 0; i < 4; i++)
        #pragma unroll
        for (int j = 0; j < 8; j++)
            #pragma unroll
            for (int c = 0; c < 4; c++) acc[i][j][c] = 0.f;

    const int nk = K >> 6;

    #pragma unroll
    for (int p = 0; p < 2; p++) {
        uint32_t st = sbase + (uint32_t)p * STG_BYTES;
        load_tile128(Ahi, K, rowBase, p * 64, st,          tid);
        load_tile128(Alo, K, rowBase, p * 64, st + OFF_AL, tid);
        load_tile256(Bhi, K, colBase, p * 64, st + OFF_BH, tid);
        load_tile256(Blo, K, colBase, p * 64, st + OFF_BL, tid);
        cp_commit();
    }

    const int aRowL = wm + (lane & 15);
    const int aSel  = (lane >> 4);
    const int bRowL = wn + (lane & 7) + ((lane >> 4) << 3);
    const int bSel  = (lane >> 3) & 1;

    for (int i = 0; i < nk; i++) {
        if (i == nk - 1) cp_wait<0>(); else cp_wait<1>();
        __syncthreads();

        const uint32_t sA  = sbase + (uint32_t)(i & 1) * STG_BYTES;
        const uint32_t sAl = sA + OFF_AL;
        const uint32_t sBh = sA + OFF_BH;
        const uint32_t sBl = sA + OFF_BL;

        #pragma unroll
        for (int kk = 0; kk < 4; kk++) {
            const int aCb = kk * 32 + aSel * 16;
            const int bCb = kk * 32 + bSel * 16;

            uint32_t af[16], bhf[16], blf[16];
            #pragma unroll
            for (int mi = 0; mi < 4; mi++)
                ldsm4(&af[mi * 4], swaddr(sA, aRowL + mi * 16, aCb));
            #pragma unroll
            for (int p = 0; p < 4; p++) {
                ldsm4(&bhf[p * 4], swaddr(sBh, bRowL + p * 16, bCb));
                ldsm4(&blf[p * 4], swaddr(sBl, bRowL + p * 16, bCb));
            }
            // hi*hi and hi*lo
            #pragma unroll
            for (int mi = 0; mi < 4; mi++)
                #pragma unroll
                for (int ni = 0; ni < 8; ni++) {
                    mma16816(acc[mi][ni], &af[mi * 4], &bhf[ni * 2]);
                    mma16816(acc[mi][ni], &af[mi * 4], &blf[ni * 2]);
                }
            // lo*hi
            #pragma unroll
            for (int mi = 0; mi < 4; mi++)
                ldsm4(&af[mi * 4], swaddr(sAl, aRowL + mi * 16, aCb));
            #pragma unroll
            for (int mi = 0; mi < 4; mi++)
                #pragma unroll
                for (int ni = 0; ni < 8; ni++)
                    mma16816(acc[mi][ni], &af[mi * 4], &bhf[ni * 2]);
        }

        if (i + 2 < nk) {
            __syncthreads();
            const int k0 = (i + 2) << 6;
            uint32_t st = sbase + (uint32_t)(i & 1) * STG_BYTES;
            load_tile128(Ahi, K, rowBase, k0, st,          tid);
            load_tile128(Alo, K, rowBase, k0, st + OFF_AL, tid);
            load_tile256(Bhi, K, colBase, k0, st + OFF_BH, tid);
            load_tile256(Blo, K, colBase, k0, st + OFF_BL, tid);
            cp_commit();
        }
    }

    // epilogue
    #pragma unroll
    for (int mi = 0; mi < 4; mi++) {
        #pragma unroll
        for (int ni = 0; ni < 8; ni++) {
            const int col = colBase + wn + ni * 8 + (lane & 3) * 2;
            if (col < N) {
                const float2 bv = *(const float2*)(bias + col);
                #pragma unroll
                for (int h = 0; h < 2; h++) {
                    const int row = rowBase + wm + mi * 16 + (lane >> 2) + h * 8;
                    float v0 = acc[mi][ni][h * 2 + 0] + bv.x;
                    float v1 = acc[mi][ni][h * 2 + 1] + bv.y;
                    if (OUTMODE == 0) {
                        v0 = fmaxf(v0, 0.f);
                        v1 = fmaxf(v1, 0.f);
                        __nv_bfloat16 h0 = __float2bfloat16(v0);
                        __nv_bfloat16 h1 = __float2bfloat16(v1);
                        __nv_bfloat16 l0 = __float2bfloat16(v0 - __bfloat162float(h0));
                        __nv_bfloat16 l1 = __float2bfloat16(v1 - __bfloat162float(h1));
                        __nv_bfloat162 ph; ph.x = h0; ph.y = h1;
                        __nv_bfloat162 pl; pl.x = l0; pl.y = l1;
                        *(uint32_t*)(Chi + (size_t)row * N + col) = *(uint32_t*)&ph;
                        *(uint32_t*)(Clo + (size_t)row * N + col) = *(uint32_t*)&pl;
                    } else {
                        float2 v; v.x = v0; v.y = v1;
                        *(float2*)(Cf + (size_t)row * N + col) = v;
                    }
                }
            }
        }
    }
}

// ---------------- per-row softmax stats (both branches, y = branch), float4 ----------------
__global__ void rowstats2_kernel(const float* __restrict__ lg0, const float* __restrict__ lg1,
                                 float2* __restrict__ st0, float2* __restrict__ st1,
                                 int nc0, int nc1)
{
    int r = blockIdx.x;
    if (r >= g_Meff) return;
    const float* p = blockIdx.y ? lg1 : lg0;
    float2* stats  = blockIdx.y ? st1 : st0;
    const int ncols = blockIdx.y ? nc1 : nc0;
    const float4* p4 = (const float4*)(p + (size_t)r * ncols);
    const int nv = ncols >> 2;
    const int tid = threadIdx.x;     // 128
    __shared__ float red[128];

    float mx = -3.402823466e38f;
    for (int j = tid; j < nv; j += 128) {
        float4 v = p4[j];
        mx = fmaxf(mx, fmaxf(fmaxf(v.x, v.y), fmaxf(v.z, v.w)));
    }
    red[tid] = mx; __syncthreads();
    for (int s = 64; s; s >>= 1) {
        if (tid < s) red[tid] = fmaxf(red[tid], red[tid + s]);
        __syncthreads();
    }
    mx = red[0]; __syncthreads();

    float sum = 0.f;
    for (int j = tid; j < nv; j += 128) {
        float4 v = p4[j];
        sum += expf(v.x - mx) + expf(v.y - mx) + expf(v.z - mx) + expf(v.w - mx);
    }
    red[tid] = sum; __syncthreads();
    for (int s = 64; s; s >>= 1) {
        if (tid < s) red[tid] += red[tid + s];
        __syncthreads();
    }
    if (tid == 0) stats[r] = make_float2(mx, red[0]);
}

// ---------------- fused score(argmax) + gather: one block per label ----------------
__global__ void scoregather_kernel(const int* __restrict__ label_img,
                                   const int* __restrict__ obj_labels,
                                   const int* __restrict__ att_labels,
                                   const int* __restrict__ num_descs,
                                   float* __restrict__ out)
{
    int l = blockIdx.x;
    int b = label_img[l];
    int nd = num_descs[b];
    int oj = obj_labels[l];
    int aj = att_labels[l];
    int rs = g_rowstart[b];
    const int tid = threadIdx.x;   // 256

    // --- per-label argmax over n < nd (first-max tie-break) ---
    __shared__ float sval[256];
    __shared__ int   sidx[256];
    float best = -1.0f;            // valid scores are >= 0; nd==0 -> idx 0
    int   bidx = 0;
    for (int n = tid; n < nd; n += 256) {
        int r = rs + n;
        float2 so = g_st_o[r];
        float2 sa = g_st_a[r];
        float po = expf(g_lo[(size_t)r * OO  + oj] - so.x) / so.y;
        float pa = expf(g_la[(size_t)r * AAd + aj] - sa.x) / sa.y;
        float s = po * pa;
        if (s > best || (s == best && n < bidx)) { best = s; bidx = n; }
    }
    sval[tid] = best; sidx[tid] = bidx;
    __syncthreads();
    for (int s = 128; s; s >>= 1) {
        if (tid < s) {
            float ov = sval[tid + s];
            int   oi = sidx[tid + s];
            if (ov > sval[tid] || (ov == sval[tid] && oi < sidx[tid])) {
                sval[tid] = ov; sidx[tid] = oi;
            }
        }
        __syncthreads();
    }
    const int r = rs + sidx[0];

    // --- gather: softmax of selected row, float4 ---
    float2 so = g_st_o[r];
    float inv_o = 1.0f / so.y;
    const float4* lo4 = (const float4*)(g_lo + (size_t)r * OO);
    float4* oo4 = (float4*)(out + (size_t)l * OO);
    for (int j = tid; j < OO / 4; j += 256) {
        float4 v = lo4[j];
        float4 w;
        w.x = expf(v.x - so.x) * inv_o;
        w.y = expf(v.y - so.x) * inv_o;
        w.z = expf(v.z - so.x) * inv_o;
        w.w = expf(v.w - so.x) * inv_o;
        oo4[j] = w;
    }

    float2 sa = g_st_a[r];
    float inv_a = 1.0f / sa.y;
    const float4* la4 = (const float4*)(g_la + (size_t)r * AAd);
    float4* oa4 = (float4*)(out + (size_t)LL * OO + (size_t)l * AAd);
    for (int j = tid; j < AAd / 4; j += 256) {
        float4 v = la4[j];
        float4 w;
        w.x = expf(v.x - sa.x) * inv_a;
        w.y = expf(v.y - sa.x) * inv_a;
        w.z = expf(v.z - sa.x) * inv_a;
        w.w = expf(v.w - sa.x) * inv_a;
        oa4[j] = w;
    }
}

// ---------------- launch ----------------
extern "C" void kernel_launch(void* const* d_in, const int* in_sizes, int n_in,
                              void* d_out, int out_size)
{
    const float* x          = (const float*)d_in[0];
    const int*   num_descs  = (const int*)  d_in[1];
    const int*   label_img  = (const int*)  d_in[2];
    const int*   obj_labels = (const int*)  d_in[3];
    const int*   att_labels = (const int*)  d_in[4];
    const float* w1o = (const float*)d_in[5];
    const float* b1o = (const float*)d_in[6];
    const float* w2o = (const float*)d_in[7];
    const float* b2o = (const float*)d_in[8];
    const float* w3o = (const float*)d_in[9];
    const float* b3o = (const float*)d_in[10];
    const float* w1a = (const float*)d_in[11];
    const float* b1a = (const float*)d_in[12];
    const float* w2a = (const float*)d_in[13];
    const float* b2a = (const float*)d_in[14];
    const float* w3a = (const float*)d_in[15];
    const float* b3a = (const float*)d_in[16];
    float* out = (float*)d_out;

    __nv_bfloat16 *xch, *xcl;
    __nv_bfloat16 *h1oh, *h1ol, *h1ah, *h1al, *h2oh, *h2ol, *h2ah, *h2al;
    __nv_bfloat16 *w1oh, *w1ol, *w2oh, *w2ol, *w3oh, *w3ol;
    __nv_bfloat16 *w1ah, *w1al, *w2ah, *w2al, *w3ah, *w3al;
    float *lo, *la;
    float2 *sto, *sta;
    cudaGetSymbolAddress((void**)&xch, g_xc_hi);   cudaGetSymbolAddress((void**)&xcl, g_xc_lo);
    cudaGetSymbolAddress((void**)&h1oh, g_h1o_hi); cudaGetSymbolAddress((void**)&h1ol, g_h1o_lo);
    cudaGetSymbolAddress((void**)&h1ah, g_h1a_hi); cudaGetSymbolAddress((void**)&h1al, g_h1a_lo);
    cudaGetSymbolAddress((void**)&h2oh, g_h2o_hi); cudaGetSymbolAddress((void**)&h2ol, g_h2o_lo);
    cudaGetSymbolAddress((void**)&h2ah, g_h2a_hi); cudaGetSymbolAddress((void**)&h2al, g_h2a_lo);
    cudaGetSymbolAddress((void**)&w1oh, g_wt1o_hi); cudaGetSymbolAddress((void**)&w1ol, g_wt1o_lo);
    cudaGetSymbolAddress((void**)&w2oh, g_wt2o_hi); cudaGetSymbolAddress((void**)&w2ol, g_wt2o_lo);
    cudaGetSymbolAddress((void**)&w3oh, g_wt3o_hi); cudaGetSymbolAddress((void**)&w3ol, g_wt3o_lo);
    cudaGetSymbolAddress((void**)&w1ah, g_wt1a_hi); cudaGetSymbolAddress((void**)&w1al, g_wt1a_lo);
    cudaGetSymbolAddress((void**)&w2ah, g_wt2a_hi); cudaGetSymbolAddress((void**)&w2al, g_wt2a_lo);
    cudaGetSymbolAddress((void**)&w3ah, g_wt3a_hi); cudaGetSymbolAddress((void**)&w3al, g_wt3a_lo);
    cudaGetSymbolAddress((void**)&lo,  g_lo);
    cudaGetSymbolAddress((void**)&la,  g_la);
    cudaGetSymbolAddress((void**)&sto, g_st_o);
    cudaGetSymbolAddress((void**)&sta, g_st_a);

    cudaFuncSetAttribute(hgemm<0>, cudaFuncAttributeMaxDynamicSharedMemorySize, GEMM_SMEM);
    cudaFuncSetAttribute(hgemm<1>, cudaFuncAttributeMaxDynamicSharedMemorySize, GEMM_SMEM);

    const int MT = MM / 128;  // 100 M tiles max; blocks past g_Meff exit
    dim3 wb(32, 8);

    // 1
    setup_kernel<<<1, BB>>>(num_descs);
    // 2
    xsplit_kernel<<<MM, 256>>>(x);
    // 3: w1 prep, both branches
    wsplit2_kernel<<<dim3(HH/32, DD/32, 2), wb>>>(w1o, w1a, w1oh, w1ol, w1ah, w1al, DD, HH, HH, HH, HH);
    // 4: layer-1 GEMM (profiled by ncu)
    GArgs a1 = { xch, xcl, w1oh, w1ol,
                 xch, xcl, w1ah, w1al,
                 b1o, b1a, nullptr, nullptr,
                 h1oh, h1ol, h1ah, h1al, HH, HH, DD };
    hgemm<0><<<dim3(HH/256, MT, 2), 256, GEMM_SMEM>>>(a1);
    // 5
    wsplit2_kernel<<<dim3(HH/32, HH/32, 2), wb>>>(w2o, w2a, w2oh, w2ol, w2ah, w2al, HH, HH, HH, HH, HH);
    // 6: layer-2 GEMM
    GArgs a2 = { h1oh, h1ol, w2oh, w2ol,
                 h1ah, h1al, w2ah, w2al,
                 b2o, b2a, nullptr, nullptr,
                 h2oh, h2ol, h2ah, h2al, HH, HH, HH };
    hgemm<0><<<dim3(HH/256, MT, 2), 256, GEMM_SMEM>>>(a2);
    // 7: w3 prep, both branches in one launch (pads zeroed; att blocks past APAD exit)
    wsplit2_kernel<<<dim3(OPAD/32, HH/32, 2), wb>>>(w3o, w3a, w3oh, w3ol, w3ah, w3al, HH, OO, AAd, OPAD, APAD);
    // 8: layer-3, both branches merged (z=0 obj N=OO, z=1 att N=AAd)
    GArgs a3 = { h2oh, h2ol, w3oh, w3ol,
                 h2ah, h2al, w3ah, w3al,
                 b3o, b3a, lo, la,
                 nullptr, nullptr, nullptr, nullptr, OO, AAd, HH };
    hgemm<1><<<dim3(OPAD/256, MT, 2), 256, GEMM_SMEM>>>(a3);

    // 9: stats, 10: fused argmax+gather
    rowstats2_kernel<<<dim3(MM, 2), 128>>>(lo, la, sto, sta, OO, AAd);
    scoregather_kernel<<<LL, 256>>>(label_img, obj_labels, att_labels, num_descs, out);
}

// round 16
// speedup vs baseline: 1.5430x; 1.0045x over previous
#include <cuda_runtime.h>
#include <cuda_bf16.h>
#include <math.h>
#include <stdint.h>

// Problem constants
#define BB 128
#define NN 100
#define DD 2048
#define HH 1024
#define OO 1600
#define AAd 400
#define LL 2048
#define MM (BB*NN)   // 12800

#define OPAD 1792    // OO padded to 256
#define APAD 512     // AAd padded to 256

// ---------------- device scratch (no allocs allowed) ----------------
__device__ __nv_bfloat16 g_xc_hi[(size_t)MM * DD];
__device__ __nv_bfloat16 g_xc_lo[(size_t)MM * DD];
__device__ __nv_bfloat16 g_h1o_hi[(size_t)MM * HH];
__device__ __nv_bfloat16 g_h1o_lo[(size_t)MM * HH];
__device__ __nv_bfloat16 g_h1a_hi[(size_t)MM * HH];
__device__ __nv_bfloat16 g_h1a_lo[(size_t)MM * HH];
__device__ __nv_bfloat16 g_h2o_hi[(size_t)MM * HH];
__device__ __nv_bfloat16 g_h2o_lo[(size_t)MM * HH];
__device__ __nv_bfloat16 g_h2a_hi[(size_t)MM * HH];
__device__ __nv_bfloat16 g_h2a_lo[(size_t)MM * HH];
__device__ __nv_bfloat16 g_wt1o_hi[(size_t)HH * DD];
__device__ __nv_bfloat16 g_wt1o_lo[(size_t)HH * DD];
__device__ __nv_bfloat16 g_wt2o_hi[(size_t)HH * HH];
__device__ __nv_bfloat16 g_wt2o_lo[(size_t)HH * HH];
__device__ __nv_bfloat16 g_wt3o_hi[(size_t)OPAD * HH];
__device__ __nv_bfloat16 g_wt3o_lo[(size_t)OPAD * HH];
__device__ __nv_bfloat16 g_wt1a_hi[(size_t)HH * DD];
__device__ __nv_bfloat16 g_wt1a_lo[(size_t)HH * DD];
__device__ __nv_bfloat16 g_wt2a_hi[(size_t)HH * HH];
__device__ __nv_bfloat16 g_wt2a_lo[(size_t)HH * HH];
__device__ __nv_bfloat16 g_wt3a_hi[(size_t)APAD * HH];
__device__ __nv_bfloat16 g_wt3a_lo[(size_t)APAD * HH];
__device__ float g_lo[(size_t)MM * OO];
__device__ float g_la[(size_t)MM * AAd];
__device__ float2 g_st_o[MM];
__device__ float2 g_st_a[MM];
__device__ int   g_rowmap[MM];
__device__ int   g_rowstart[BB];
__device__ int   g_Meff;

// ---------------- PTX helpers (baseline sm_80+ features only) ----------------
__device__ __forceinline__ uint32_t smem_u32_of(const void* p) {
    uint32_t a;
    asm("{ .reg .u64 t; cvta.to.shared.u64 t, %1; cvt.u32.u64 %0, t; }" : "=r"(a) : "l"(p));
    return a;
}
__device__ __forceinline__ void cp16(uint32_t dst, const void* src) {
    asm volatile("cp.async.cg.shared.global [%0], [%1], 16;" :: "r"(dst), "l"(src) : "memory");
}
__device__ __forceinline__ void cp_commit() {
    asm volatile("cp.async.commit_group;" ::: "memory");
}
template<int N>
__device__ __forceinline__ void cp_wait() {
    asm volatile("cp.async.wait_group %0;" :: "n"(N) : "memory");
}
__device__ __forceinline__ void ldsm4(uint32_t* r, uint32_t addr) {
    asm volatile("ldmatrix.sync.aligned.m8n8.x4.shared.b16 {%0,%1,%2,%3}, [%4];"
        : "=r"(r[0]), "=r"(r[1]), "=r"(r[2]), "=r"(r[3]) : "r"(addr));
}
__device__ __forceinline__ void mma16816(float* c, const uint32_t* a, const uint32_t* b) {
    asm volatile("mma.sync.aligned.m16n8k16.row.col.f32.bf16.bf16.f32 "
        "{%0,%1,%2,%3}, {%4,%5,%6,%7}, {%8,%9}, {%0,%1,%2,%3};"
        : "+f"(c[0]), "+f"(c[1]), "+f"(c[2]), "+f"(c[3])
        : "r"(a[0]), "r"(a[1]), "r"(a[2]), "r"(a[3]), "r"(b[0]), "r"(b[1]));
}

// ---------------- setup: live-row compaction ----------------
__global__ void setup_kernel(const int* __restrict__ num_descs) {
    __shared__ int cnt[BB];
    int b = threadIdx.x;
    int c = num_descs[b];
    if (c < 1) c = 1;
    cnt[b] = c;
    __syncthreads();
    if (b == 0) {
        int acc = 0;
        for (int i = 0; i < BB; i++) { g_rowstart[i] = acc; acc += cnt[i]; }
        g_Meff = acc;
    }
    __syncthreads();
    int start = g_rowstart[b];
    for (int i = 0; i < c; i++) g_rowmap[start + i] = b * NN + i;
}

// ---------------- x compaction + bf16 hi/lo split ----------------
__global__ void xsplit_kernel(const float* __restrict__ x) {
    int r = blockIdx.x;
    int Meff = g_Meff;
    int mceil = (Meff + 127) & ~127;
    if (r >= mceil) return;
    int src = g_rowmap[r < Meff ? r : (Meff - 1)];
    const float4* xp = (const float4*)(x + (size_t)src * DD);
    uint32_t* dh = (uint32_t*)(g_xc_hi + (size_t)r * DD);
    uint32_t* dl = (uint32_t*)(g_xc_lo + (size_t)r * DD);
    for (int i = threadIdx.x; i < DD / 4; i += 256) {
        float4 v = xp[i];
        __nv_bfloat16 h0 = __float2bfloat16(v.x);
        __nv_bfloat16 h1 = __float2bfloat16(v.y);
        __nv_bfloat16 h2 = __float2bfloat16(v.z);
        __nv_bfloat16 h3 = __float2bfloat16(v.w);
        __nv_bfloat16 l0 = __float2bfloat16(v.x - __bfloat162float(h0));
        __nv_bfloat16 l1 = __float2bfloat16(v.y - __bfloat162float(h1));
        __nv_bfloat16 l2 = __float2bfloat16(v.z - __bfloat162float(h2));
        __nv_bfloat16 l3 = __float2bfloat16(v.w - __bfloat162float(h3));
        __nv_bfloat162 ph0; ph0.x = h0; ph0.y = h1;
        __nv_bfloat162 ph1; ph1.x = h2; ph1.y = h3;
        __nv_bfloat162 pl0; pl0.x = l0; pl0.y = l1;
        __nv_bfloat162 pl1; pl1.x = l2; pl1.y = l3;
        dh[2*i]   = *(uint32_t*)&ph0;
        dh[2*i+1] = *(uint32_t*)&ph1;
        dl[2*i]   = *(uint32_t*)&pl0;
        dl[2*i+1] = *(uint32_t*)&pl1;
    }
}

// ---------------- ALL weight transpose+split in ONE launch (z = matrix id) ----------------
struct WArgs {
    const float* W[6];
    __nv_bfloat16* Th[6];
    __nv_bfloat16* Tl[6];
    int K[6], N[6], NP[6];
};

__global__ void wsplit_all_kernel(WArgs a) {
    const int zi = blockIdx.z;
    const float* W = a.W[zi];
    __nv_bfloat16* Th = a.Th[zi];
    __nv_bfloat16* Tl = a.Tl[zi];
    const int K  = a.K[zi];
    const int N  = a.N[zi];
    const int NP = a.NP[zi];
    int n0 = blockIdx.x * 32, k0 = blockIdx.y * 32;
    if (n0 >= NP || k0 >= K) return;
    __shared__ float t[32][33];
    int tx = threadIdx.x, ty = threadIdx.y;
    for (int i = ty; i < 32; i += 8) {
        int n = n0 + tx;
        t[i][tx] = (n < N) ? W[(size_t)(k0 + i) * N + n] : 0.f;
    }
    __syncthreads();
    for (int i = ty; i < 32; i += 8) {
        int n = n0 + i;
        float v = t[tx][i];
        __nv_bfloat16 h = __float2bfloat16(v);
        Th[(size_t)n * K + k0 + tx] = h;
        Tl[(size_t)n * K + k0 + tx] = __float2bfloat16(v - __bfloat162float(h));
    }
}

// ---------------- HMMA split-bf16 GEMM (8 warps of 64x64) ----------------
// Block tile 128x256, 256 threads = 8 warps (2M x 4N) of 64x64 each.
// K-chunk 64, 2-stage cp.async, two barriers per chunk (best measured config).
#define STG_BYTES 98304u
#define GEMM_SMEM (2 * 98304)
#define OFF_AL 16384u
#define OFF_BH 32768u
#define OFF_BL 65536u

struct GArgs {
    const __nv_bfloat16 *Ahi0, *Alo0, *Bhi0, *Blo0;
    const __nv_bfloat16 *Ahi1, *Alo1, *Bhi1, *Blo1;
    const float *bias0, *bias1;
    float *Cf0, *Cf1;
    __nv_bfloat16 *Chi0, *Clo0, *Chi1, *Clo1;
    int N0, N1, K;
};

// 128 rows x 64 cols bf16 -> swizzled smem (256 threads, 4 chunks each)
__device__ __forceinline__ void load_tile128(const __nv_bfloat16* __restrict__ g,
                                             int rowStride, int row0, int k0,
                                             uint32_t sdst, int tid) {
    #pragma unroll
    for (int it = 0; it < 4; it++) {
        int v = tid + it * 256;
        int r = v >> 3, cv = v & 7;
        const void* src = g + (size_t)(row0 + r) * rowStride + k0 + cv * 8;
        uint32_t cb = (uint32_t)(cv * 16);
        uint32_t sw = (uint32_t)(r * 128) + (cb ^ (((uint32_t)r & 7u) << 4));
        cp16(sdst + sw, src);
    }
}
// 256 rows x 64 cols bf16 (8 chunks each)
__device__ __forceinline__ void load_tile256(const __nv_bfloat16* __restrict__ g,
                                             int rowStride, int row0, int k0,
                                             uint32_t sdst, int tid) {
    #pragma unroll
    for (int it = 0; it < 8; it++) {
        int v = tid + it * 256;
        int r = v >> 3, cv = v & 7;
        const void* src = g + (size_t)(row0 + r) * rowStride + k0 + cv * 8;
        uint32_t cb = (uint32_t)(cv * 16);
        uint32_t sw = (uint32_t)(r * 128) + (cb ^ (((uint32_t)r & 7u) << 4));
        cp16(sdst + sw, src);
    }
}

__device__ __forceinline__ uint32_t swaddr(uint32_t base, int row, int cb) {
    return base + (uint32_t)(row * 128) + (((uint32_t)cb) ^ (((uint32_t)row & 7u) << 4));
}

// OUTMODE 0: relu + bf16 hi/lo outputs.  OUTMODE 1: fp32 outputs, no relu.
template<int OUTMODE>
__global__ __launch_bounds__(256, 1)
void hgemm(GArgs g)
{
    const int Meff = g_Meff;
    const int rowBase = blockIdx.y * 128;
    if (rowBase >= Meff) return;
    const int z = blockIdx.z;
    const int N = z ? g.N1 : g.N0;
    const int colBase = blockIdx.x * 256;
    if (colBase >= ((N + 255) & ~255)) return;

    const int tid = threadIdx.x;
    const __nv_bfloat16* Ahi = z ? g.Ahi1 : g.Ahi0;
    const __nv_bfloat16* Alo = z ? g.Alo1 : g.Alo0;
    const __nv_bfloat16* Bhi = z ? g.Bhi1 : g.Bhi0;
    const __nv_bfloat16* Blo = z ? g.Blo1 : g.Blo0;
    const float* bias        = z ? g.bias1 : g.bias0;
    float* Cf                = z ? g.Cf1 : g.Cf0;
    __nv_bfloat16* Chi       = z ? g.Chi1 : g.Chi0;
    __nv_bfloat16* Clo       = z ? g.Clo1 : g.Clo0;
    const int K = g.K;

    extern __shared__ char smem[];
    const uint32_t sbase = smem_u32_of(smem);

    const int warp = tid >> 5, lane = tid & 31;
    const int wm = (warp >> 2) * 64;      // 0 / 64
    const int wn = (warp & 3) * 64;       // 0 / 64 / 128 / 192

    float acc[4][8][4];
    #pragma unroll
    for (int i = 0; i < 4; i++)
        #pragma unroll
        for (int j = 0; j < 8; j++)
            #pragma unroll
            for (int c = 0; c < 4; c++) acc[i][j][c] = 0.f;

    const int nk = K >> 6;

    #pragma unroll
    for (int p = 0; p < 2; p++) {
        uint32_t st = sbase + (uint32_t)p * STG_BYTES;
        load_tile128(Ahi, K, rowBase, p * 64, st,          tid);
        load_tile128(Alo, K, rowBase, p * 64, st + OFF_AL, tid);
        load_tile256(Bhi, K, colBase, p * 64, st + OFF_BH, tid);
        load_tile256(Blo, K, colBase, p * 64, st + OFF_BL, tid);
        cp_commit();
    }

    const int aRowL = wm + (lane & 15);
    const int aSel  = (lane >> 4);
    const int bRowL = wn + (lane & 7) + ((lane >> 4) << 3);
    const int bSel  = (lane >> 3) & 1;

    for (int i = 0; i < nk; i++) {
        if (i == nk - 1) cp_wait<0>(); else cp_wait<1>();
        __syncthreads();

        const uint32_t sA  = sbase + (uint32_t)(i & 1) * STG_BYTES;
        const uint32_t sAl = sA + OFF_AL;
        const uint32_t sBh = sA + OFF_BH;
        const uint32_t sBl = sA + OFF_BL;

        #pragma unroll
        for (int kk = 0; kk < 4; kk++) {
            const int aCb = kk * 32 + aSel * 16;
            const int bCb = kk * 32 + bSel * 16;

            uint32_t af[16], bhf[16], blf[16];
            #pragma unroll
            for (int mi = 0; mi < 4; mi++)
                ldsm4(&af[mi * 4], swaddr(sA, aRowL + mi * 16, aCb));
            #pragma unroll
            for (int p = 0; p < 4; p++) {
                ldsm4(&bhf[p * 4], swaddr(sBh, bRowL + p * 16, bCb));
                ldsm4(&blf[p * 4], swaddr(sBl, bRowL + p * 16, bCb));
            }
            // hi*hi and hi*lo
            #pragma unroll
            for (int mi = 0; mi < 4; mi++)
                #pragma unroll
                for (int ni = 0; ni < 8; ni++) {
                    mma16816(acc[mi][ni], &af[mi * 4], &bhf[ni * 2]);
                    mma16816(acc[mi][ni], &af[mi * 4], &blf[ni * 2]);
                }
            // lo*hi
            #pragma unroll
            for (int mi = 0; mi < 4; mi++)
                ldsm4(&af[mi * 4], swaddr(sAl, aRowL + mi * 16, aCb));
            #pragma unroll
            for (int mi = 0; mi < 4; mi++)
                #pragma unroll
                for (int ni = 0; ni < 8; ni++)
                    mma16816(acc[mi][ni], &af[mi * 4], &bhf[ni * 2]);
        }

        if (i + 2 < nk) {
            __syncthreads();
            const int k0 = (i + 2) << 6;
            uint32_t st = sbase + (uint32_t)(i & 1) * STG_BYTES;
            load_tile128(Ahi, K, rowBase, k0, st,          tid);
            load_tile128(Alo, K, rowBase, k0, st + OFF_AL, tid);
            load_tile256(Bhi, K, colBase, k0, st + OFF_BH, tid);
            load_tile256(Blo, K, colBase, k0, st + OFF_BL, tid);
            cp_commit();
        }
    }

    // epilogue
    #pragma unroll
    for (int mi = 0; mi < 4; mi++) {
        #pragma unroll
        for (int ni = 0; ni < 8; ni++) {
            const int col = colBase + wn + ni * 8 + (lane & 3) * 2;
            if (col < N) {
                const float2 bv = *(const float2*)(bias + col);
                #pragma unroll
                for (int h = 0; h < 2; h++) {
                    const int row = rowBase + wm + mi * 16 + (lane >> 2) + h * 8;
                    float v0 = acc[mi][ni][h * 2 + 0] + bv.x;
                    float v1 = acc[mi][ni][h * 2 + 1] + bv.y;
                    if (OUTMODE == 0) {
                        v0 = fmaxf(v0, 0.f);
                        v1 = fmaxf(v1, 0.f);
                        __nv_bfloat16 h0 = __float2bfloat16(v0);
                        __nv_bfloat16 h1 = __float2bfloat16(v1);
                        __nv_bfloat16 l0 = __float2bfloat16(v0 - __bfloat162float(h0));
                        __nv_bfloat16 l1 = __float2bfloat16(v1 - __bfloat162float(h1));
                        __nv_bfloat162 ph; ph.x = h0; ph.y = h1;
                        __nv_bfloat162 pl; pl.x = l0; pl.y = l1;
                        *(uint32_t*)(Chi + (size_t)row * N + col) = *(uint32_t*)&ph;
                        *(uint32_t*)(Clo + (size_t)row * N + col) = *(uint32_t*)&pl;
                    } else {
                        float2 v; v.x = v0; v.y = v1;
                        *(float2*)(Cf + (size_t)row * N + col) = v;
                    }
                }
            }
        }
    }
}

// ---------------- per-row softmax stats (both branches, y = branch), float4 ----------------
__global__ void rowstats2_kernel(const float* __restrict__ lg0, const float* __restrict__ lg1,
                                 float2* __restrict__ st0, float2* __restrict__ st1,
                                 int nc0, int nc1)
{
    int r = blockIdx.x;
    if (r >= g_Meff) return;
    const float* p = blockIdx.y ? lg1 : lg0;
    float2* stats  = blockIdx.y ? st1 : st0;
    const int ncols = blockIdx.y ? nc1 : nc0;
    const float4* p4 = (const float4*)(p + (size_t)r * ncols);
    const int nv = ncols >> 2;
    const int tid = threadIdx.x;     // 128
    __shared__ float red[128];

    float mx = -3.402823466e38f;
    for (int j = tid; j < nv; j += 128) {
        float4 v = p4[j];
        mx = fmaxf(mx, fmaxf(fmaxf(v.x, v.y), fmaxf(v.z, v.w)));
    }
    red[tid] = mx; __syncthreads();
    for (int s = 64; s; s >>= 1) {
        if (tid < s) red[tid] = fmaxf(red[tid], red[tid + s]);
        __syncthreads();
    }
    mx = red[0]; __syncthreads();

    float sum = 0.f;
    for (int j = tid; j < nv; j += 128) {
        float4 v = p4[j];
        sum += expf(v.x - mx) + expf(v.y - mx) + expf(v.z - mx) + expf(v.w - mx);
    }
    red[tid] = sum; __syncthreads();
    for (int s = 64; s; s >>= 1) {
        if (tid < s) red[tid] += red[tid + s];
        __syncthreads();
    }
    if (tid == 0) stats[r] = make_float2(mx, red[0]);
}

// ---------------- fused score(argmax) + gather: one block per label ----------------
__global__ void scoregather_kernel(const int* __restrict__ label_img,
                                   const int* __restrict__ obj_labels,
                                   const int* __restrict__ att_labels,
                                   const int* __restrict__ num_descs,
                                   float* __restrict__ out)
{
    int l = blockIdx.x;
    int b = label_img[l];
    int nd = num_descs[b];
    int oj = obj_labels[l];
    int aj = att_labels[l];
    int rs = g_rowstart[b];
    const int tid = threadIdx.x;   // 256

    __shared__ float sval[256];
    __shared__ int   sidx[256];
    float best = -1.0f;
    int   bidx = 0;
    for (int n = tid; n < nd; n += 256) {
        int r = rs + n;
        float2 so = g_st_o[r];
        float2 sa = g_st_a[r];
        float po = expf(g_lo[(size_t)r * OO  + oj] - so.x) / so.y;
        float pa = expf(g_la[(size_t)r * AAd + aj] - sa.x) / sa.y;
        float s = po * pa;
        if (s > best || (s == best && n < bidx)) { best = s; bidx = n; }
    }
    sval[tid] = best; sidx[tid] = bidx;
    __syncthreads();
    for (int s = 128; s; s >>= 1) {
        if (tid < s) {
            float ov = sval[tid + s];
            int   oi = sidx[tid + s];
            if (ov > sval[tid] || (ov == sval[tid] && oi < sidx[tid])) {
                sval[tid] = ov; sidx[tid] = oi;
            }
        }
        __syncthreads();
    }
    const int r = rs + sidx[0];

    float2 so = g_st_o[r];
    float inv_o = 1.0f / so.y;
    const float4* lo4 = (const float4*)(g_lo + (size_t)r * OO);
    float4* oo4 = (float4*)(out + (size_t)l * OO);
    for (int j = tid; j < OO / 4; j += 256) {
        float4 v = lo4[j];
        float4 w;
        w.x = expf(v.x - so.x) * inv_o;
        w.y = expf(v.y - so.x) * inv_o;
        w.z = expf(v.z - so.x) * inv_o;
        w.w = expf(v.w - so.x) * inv_o;
        oo4[j] = w;
    }

    float2 sa = g_st_a[r];
    float inv_a = 1.0f / sa.y;
    const float4* la4 = (const float4*)(g_la + (size_t)r * AAd);
    float4* oa4 = (float4*)(out + (size_t)LL * OO + (size_t)l * AAd);
    for (int j = tid; j < AAd / 4; j += 256) {
        float4 v = la4[j];
        float4 w;
        w.x = expf(v.x - sa.x) * inv_a;
        w.y = expf(v.y - sa.x) * inv_a;
        w.z = expf(v.z - sa.x) * inv_a;
        w.w = expf(v.w - sa.x) * inv_a;
        oa4[j] = w;
    }
}

// ---------------- launch ----------------
extern "C" void kernel_launch(void* const* d_in, const int* in_sizes, int n_in,
                              void* d_out, int out_size)
{
    const float* x          = (const float*)d_in[0];
    const int*   num_descs  = (const int*)  d_in[1];
    const int*   label_img  = (const int*)  d_in[2];
    const int*   obj_labels = (const int*)  d_in[3];
    const int*   att_labels = (const int*)  d_in[4];
    const float* w1o = (const float*)d_in[5];
    const float* b1o = (const float*)d_in[6];
    const float* w2o = (const float*)d_in[7];
    const float* b2o = (const float*)d_in[8];
    const float* w3o = (const float*)d_in[9];
    const float* b3o = (const float*)d_in[10];
    const float* w1a = (const float*)d_in[11];
    const float* b1a = (const float*)d_in[12];
    const float* w2a = (const float*)d_in[13];
    const float* b2a = (const float*)d_in[14];
    const float* w3a = (const float*)d_in[15];
    const float* b3a = (const float*)d_in[16];
    float* out = (float*)d_out;

    __nv_bfloat16 *xch, *xcl;
    __nv_bfloat16 *h1oh, *h1ol, *h1ah, *h1al, *h2oh, *h2ol, *h2ah, *h2al;
    __nv_bfloat16 *w1oh, *w1ol, *w2oh, *w2ol, *w3oh, *w3ol;
    __nv_bfloat16 *w1ah, *w1al, *w2ah, *w2al, *w3ah, *w3al;
    float *lo, *la;
    float2 *sto, *sta;
    cudaGetSymbolAddress((void**)&xch, g_xc_hi);   cudaGetSymbolAddress((void**)&xcl, g_xc_lo);
    cudaGetSymbolAddress((void**)&h1oh, g_h1o_hi); cudaGetSymbolAddress((void**)&h1ol, g_h1o_lo);
    cudaGetSymbolAddress((void**)&h1ah, g_h1a_hi); cudaGetSymbolAddress((void**)&h1al, g_h1a_lo);
    cudaGetSymbolAddress((void**)&h2oh, g_h2o_hi); cudaGetSymbolAddress((void**)&h2ol, g_h2o_lo);
    cudaGetSymbolAddress((void**)&h2ah, g_h2a_hi); cudaGetSymbolAddress((void**)&h2al, g_h2a_lo);
    cudaGetSymbolAddress((void**)&w1oh, g_wt1o_hi); cudaGetSymbolAddress((void**)&w1ol, g_wt1o_lo);
    cudaGetSymbolAddress((void**)&w2oh, g_wt2o_hi); cudaGetSymbolAddress((void**)&w2ol, g_wt2o_lo);
    cudaGetSymbolAddress((void**)&w3oh, g_wt3o_hi); cudaGetSymbolAddress((void**)&w3ol, g_wt3o_lo);
    cudaGetSymbolAddress((void**)&w1ah, g_wt1a_hi); cudaGetSymbolAddress((void**)&w1al, g_wt1a_lo);
    cudaGetSymbolAddress((void**)&w2ah, g_wt2a_hi); cudaGetSymbolAddress((void**)&w2al, g_wt2a_lo);
    cudaGetSymbolAddress((void**)&w3ah, g_wt3a_hi); cudaGetSymbolAddress((void**)&w3al, g_wt3a_lo);
    cudaGetSymbolAddress((void**)&lo,  g_lo);
    cudaGetSymbolAddress((void**)&la,  g_la);
    cudaGetSymbolAddress((void**)&sto, g_st_o);
    cudaGetSymbolAddress((void**)&sta, g_st_a);

    cudaFuncSetAttribute(hgemm<0>, cudaFuncAttributeMaxDynamicSharedMemorySize, GEMM_SMEM);
    cudaFuncSetAttribute(hgemm<1>, cudaFuncAttributeMaxDynamicSharedMemorySize, GEMM_SMEM);

    const int MT = MM / 128;  // 100 M tiles max; blocks past g_Meff exit
    dim3 wb(32, 8);

    // 1: setup
    setup_kernel<<<1, BB>>>(num_descs);

    // 2: ALL weight preps in one launch (z: w1o,w1a,w2o,w2a,w3o,w3a)
    WArgs wa;
    wa.W[0] = w1o; wa.Th[0] = w1oh; wa.Tl[0] = w1ol; wa.K[0] = DD; wa.N[0] = HH;  wa.NP[0] = HH;
    wa.W[1] = w1a; wa.Th[1] = w1ah; wa.Tl[1] = w1al; wa.K[1] = DD; wa.N[1] = HH;  wa.NP[1] = HH;
    wa.W[2] = w2o; wa.Th[2] = w2oh; wa.Tl[2] = w2ol; wa.K[2] = HH; wa.N[2] = HH;  wa.NP[2] = HH;
    wa.W[3] = w2a; wa.Th[3] = w2ah; wa.Tl[3] = w2al; wa.K[3] = HH; wa.N[3] = HH;  wa.NP[3] = HH;
    wa.W[4] = w3o; wa.Th[4] = w3oh; wa.Tl[4] = w3ol; wa.K[4] = HH; wa.N[4] = OO;  wa.NP[4] = OPAD;
    wa.W[5] = w3a; wa.Th[5] = w3ah; wa.Tl[5] = w3al; wa.K[5] = HH; wa.N[5] = AAd; wa.NP[5] = APAD;
    wsplit_all_kernel<<<dim3(OPAD/32, DD/32, 6), wb>>>(wa);

    // 3: x compact+split
    xsplit_kernel<<<MM, 256>>>(x);

    // 4: layer-1 GEMM (profiled by ncu)
    GArgs a1 = { xch, xcl, w1oh, w1ol,
                 xch, xcl, w1ah, w1al,
                 b1o, b1a, nullptr, nullptr,
                 h1oh, h1ol, h1ah, h1al, HH, HH, DD };
    hgemm<0><<<dim3(HH/256, MT, 2), 256, GEMM_SMEM>>>(a1);

    // 5: layer-2 GEMM
    GArgs a2 = { h1oh, h1ol, w2oh, w2ol,
                 h1ah, h1al, w2ah, w2al,
                 b2o, b2a, nullptr, nullptr,
                 h2oh, h2ol, h2ah, h2al, HH, HH, HH };
    hgemm<0><<<dim3(HH/256, MT, 2), 256, GEMM_SMEM>>>(a2);

    // 6: layer-3, both branches merged (z=0 obj N=OO, z=1 att N=AAd)
    GArgs a3 = { h2oh, h2ol, w3oh, w3ol,
                 h2ah, h2al, w3ah, w3al,
                 b3o, b3a, lo, la,
                 nullptr, nullptr, nullptr, nullptr, OO, AAd, HH };
    hgemm<1><<<dim3(OPAD/256, MT, 2), 256, GEMM_SMEM>>>(a3);

    // 7: stats, 8: fused argmax+gather
    rowstats2_kernel<<<dim3(MM, 2), 128>>>(lo, la, sto, sta, OO, AAd);
    scoregather_kernel<<<LL, 256>>>(label_img, obj_labels, att_labels, num_descs, out);
}